// round 3
// baseline (speedup 1.0000x reference)
#include <cuda_runtime.h>
#include <math.h>

#define BB   2
#define TT   16
#define NN   2048
#define CI1  32
#define CHH  64
#define EE   32768
#define T1   14                 /* tconv1 out / cheb time dim */
#define T2   12                 /* tconv2 out */
#define F1   (BB*T1*CHH)        /* 1792 floats per node */
#define F14  (F1/4)
#define NB_TOTAL (NN*BB)

typedef unsigned long long u64;

__device__ __forceinline__ u64 pk2(float lo, float hi) {
    u64 r; asm("mov.b64 %0, {%1, %2};" : "=l"(r) : "f"(lo), "f"(hi)); return r;
}
__device__ __forceinline__ u64 fma2(u64 a, u64 b, u64 c) {
    u64 r; asm("fma.rn.f32x2 %0, %1, %2, %3;" : "=l"(r) : "l"(a), "l"(b), "l"(c)); return r;
}
__device__ __forceinline__ float2 upk2(u64 a) {
    float2 f; asm("mov.b64 {%0, %1}, %2;" : "=f"(f.x), "=f"(f.y) : "l"(a)); return f;
}

// ---------------- scratch (layout: (nb, c, t), t contiguous) -----------------
__device__ __align__(16) float g_t1 [NB_TOTAL*CHH*T1];
__device__ __align__(16) float g_tx1[NB_TOTAL*CHH*T1];
__device__ __align__(16) float g_tx2[NB_TOTAL*CHH*T1];
__device__ __align__(16) float g_t2 [NB_TOTAL*CHH*T1];
__device__ __align__(16) float g_t3 [NB_TOTAL*CHH*T2];
__device__ float g_deg[NN];
__device__ float g_dis[NN];
__device__ int   g_rowcount[NN];
__device__ int   g_rowstart[NN+1];
__device__ int   g_cursor[NN];
__device__ int   g_ccol[EE];
__device__ float g_cnorm[EE];

// ---------------- graph preprocessing ---------------------------------------
__global__ void k_zero() {
    int i = blockIdx.x * blockDim.x + threadIdx.x;
    if (i < NN) { g_deg[i] = 0.f; g_rowcount[i] = 0; g_cursor[i] = 0; }
}

__global__ void k_deg(const int* __restrict__ ei, const float* __restrict__ ew) {
    int e = blockIdx.x * blockDim.x + threadIdx.x;
    if (e < EE) {
        int r = ei[e], c = ei[EE + e];
        float w = (r == c) ? 0.f : ew[e];
        atomicAdd(&g_deg[r], w);
        atomicAdd(&g_rowcount[r], 1);
    }
}

// scan (2048 counts) + dis computation fused; one block of 1024
__global__ void k_scandis() {
    int tid = threadIdx.x;
    // dis
    for (int i = tid; i < NN; i += 1024) {
        float d = g_deg[i];
        g_dis[i] = (d > 0.f) ? rsqrtf(d) : 0.f;
    }
    // scan
    int v0 = g_rowcount[2 * tid], v1 = g_rowcount[2 * tid + 1];
    int s  = v0 + v1;
    int lane = tid & 31, wid = tid >> 5;
    int sc = s;
#pragma unroll
    for (int o = 1; o < 32; o <<= 1) {
        int t = __shfl_up_sync(0xffffffffu, sc, o);
        if (lane >= o) sc += t;
    }
    __shared__ int ws[32];
    if (lane == 31) ws[wid] = sc;
    __syncthreads();
    if (wid == 0) {
        int w = ws[lane];
#pragma unroll
        for (int o = 1; o < 32; o <<= 1) {
            int t = __shfl_up_sync(0xffffffffu, w, o);
            if (lane >= o) w += t;
        }
        ws[lane] = w;
    }
    __syncthreads();
    int base = ((wid > 0) ? ws[wid - 1] : 0) + sc - s;
    g_rowstart[2 * tid + 1] = base + v0;
    g_rowstart[2 * tid + 2] = base + v0 + v1;
    if (tid == 0) g_rowstart[0] = 0;
}

__global__ void k_scatter(const int* __restrict__ ei, const float* __restrict__ ew) {
    int e = blockIdx.x * blockDim.x + threadIdx.x;
    if (e < EE) {
        int r = ei[e], c = ei[EE + e];
        float w = (r == c) ? 0.f : ew[e];
        int pos = g_rowstart[r] + atomicAdd(&g_cursor[r], 1);
        g_ccol[pos]  = c;
        g_cnorm[pos] = -g_dis[r] * w * g_dis[c];
    }
}

// ---------------- gated temporal conv ---------------------------------------
// 384 threads = 6 (n,b) groups x (2 t-halves x 32 co-pair lanes).
// Weights in smem as packed co-pairs, loaded in CI/CIPH phases (occupancy).
template<int CI, int TIN, int CIPH>
__global__ void __launch_bounds__(384, 2) k_tconv(
    const float* __restrict__ x, long sb, long sn, long sci, long st,
    const float* __restrict__ w1, const float* __restrict__ bb1,
    const float* __restrict__ w2, const float* __restrict__ bb2,
    const float* __restrict__ w3, const float* __restrict__ bb3,
    float* __restrict__ out)
{
    constexpr int TOUT = TIN - 2;
    constexpr int TH   = TOUT / 2;
    constexpr int NX   = TH + 2;
    constexpr int NPH  = CI / CIPH;
    extern __shared__ u64 sw[];  // [3][CIPH][3][32]

    int p  = threadIdx.x & 31;
    int h  = (threadIdx.x >> 5) & 1;
    int g  = threadIdx.x >> 6;
    int nb = blockIdx.x * 6 + g;
    bool active = (nb < NB_TOTAL);
    int n = nb >> 1, b = nb & 1;

    const float* xb = x + (long)b * sb + (long)n * sn + (long)(h * TH) * st;

    u64 acc[3][TH];
#pragma unroll
    for (int j = 0; j < 3; j++)
#pragma unroll
        for (int t = 0; t < TH; t++) acc[j][t] = 0ull;

    for (int ph = 0; ph < NPH; ph++) {
        if (ph > 0) __syncthreads();
        int ci0 = ph * CIPH;
        for (int idx = threadIdx.x; idx < 3 * CIPH * 3 * 32; idx += 384) {
            int pp = idx & 31;
            int rest = idx >> 5;
            int k = rest % 3; rest /= 3;
            int ci = rest % CIPH;
            int j  = rest / CIPH;
            const float* wj = (j == 0) ? w1 : ((j == 1) ? w2 : w3);
            sw[idx] = pk2(wj[((2 * pp)     * CI + ci0 + ci) * 3 + k],
                          wj[((2 * pp + 1) * CI + ci0 + ci) * 3 + k]);
        }
        __syncthreads();

        if (active) {
            for (int ci = 0; ci < CIPH; ci++) {
                u64 xx[NX];
#pragma unroll
                for (int i = 0; i < NX; i++) {
                    float xv = __ldg(xb + (long)(ci0 + ci) * sci + (long)i * st);
                    xx[i] = pk2(xv, xv);
                }
#pragma unroll
                for (int j = 0; j < 3; j++) {
                    u64 wk0 = sw[((j * CIPH + ci) * 3 + 0) * 32 + p];
                    u64 wk1 = sw[((j * CIPH + ci) * 3 + 1) * 32 + p];
                    u64 wk2 = sw[((j * CIPH + ci) * 3 + 2) * 32 + p];
#pragma unroll
                    for (int to = 0; to < TH; to++) {
                        acc[j][to] = fma2(xx[to],     wk0, acc[j][to]);
                        acc[j][to] = fma2(xx[to + 1], wk1, acc[j][to]);
                        acc[j][to] = fma2(xx[to + 2], wk2, acc[j][to]);
                    }
                }
            }
        }
    }

    if (active) {
        float2 bv1 = __ldg((const float2*)bb1 + p);
        float2 bv2 = __ldg((const float2*)bb2 + p);
        float2 bv3 = __ldg((const float2*)bb3 + p);
        float* ob = out + ((long)nb * 64 + 2 * p) * TOUT + h * TH;
#pragma unroll
        for (int to = 0; to < TH; to++) {
            float2 a1 = upk2(acc[0][to]);
            float2 a2 = upk2(acc[1][to]);
            float2 a3 = upk2(acc[2][to]);
            float zx = a2.x + bv2.x, zy = a2.y + bv2.y;
            float sx = __fdividef(1.f, 1.f + __expf(-zx));
            float sy = __fdividef(1.f, 1.f + __expf(-zy));
            float vx = a1.x + bv1.x + sx + a3.x + bv3.x;
            float vy = a1.y + bv1.y + sy + a3.y + bv3.y;
            ob[to]        = (vx > 0.f) ? vx : 0.f;
            ob[TOUT + to] = (vy > 0.f) ? vy : 0.f;
        }
    }
}

// ---------------- ChebConv propagation (CSR gather, layout-agnostic) --------
__global__ void k_prop(const float4* __restrict__ z, float4* __restrict__ out,
                       const float4* __restrict__ x0, int mode)
{
    int n = blockIdx.x;
    int tid = threadIdx.x;
    int e0 = g_rowstart[n], e1 = g_rowstart[n + 1];
    float4 acc = make_float4(0.f, 0.f, 0.f, 0.f);
    for (int e = e0; e < e1; e++) {
        int   c  = __ldg(&g_ccol[e]);
        float nm = __ldg(&g_cnorm[e]);
        float4 v = __ldg(&z[(long)c * F14 + tid]);
        acc.x += nm * v.x; acc.y += nm * v.y;
        acc.z += nm * v.z; acc.w += nm * v.w;
    }
    if (mode) {
        float4 v0 = __ldg(&x0[(long)n * F14 + tid]);
        acc.x = 2.f * acc.x - v0.x; acc.y = 2.f * acc.y - v0.y;
        acc.z = 2.f * acc.z - v0.z; acc.w = 2.f * acc.w - v0.w;
    }
    out[(long)n * F14 + tid] = acc;
}

// ---------------- fused Cheb GEMM, t-pair packed ------------------------------
// 512 threads = 16 nb-groups x 32 lanes; lane owns co = p and p+32.
// activations load as u64 t-pairs directly from the (nb, c, t) layout.
__global__ void __launch_bounds__(512, 2) k_cheb(const float* __restrict__ W,
                                                 const float* __restrict__ bias)
{
    extern __shared__ float sm[];
    float* sW = sm;            // [3][64][64]
    float* sb = sm + 3*64*64;
    for (int i = threadIdx.x; i < 3 * 64 * 64; i += 512) sW[i] = W[i];
    if (threadIdx.x < 64) sb[threadIdx.x] = bias[threadIdx.x];
    __syncthreads();

    int p  = threadIdx.x & 31;
    int g  = threadIdx.x >> 5;
    int nb = blockIdx.x * 16 + g;

    const u64* x0 = (const u64*)(g_t1  + (long)nb * 64 * T1);
    const u64* x1 = (const u64*)(g_tx1 + (long)nb * 64 * T1);
    const u64* x2 = (const u64*)(g_tx2 + (long)nb * 64 * T1);

    u64 acc[2][7];
#pragma unroll
    for (int q = 0; q < 2; q++)
#pragma unroll
        for (int t = 0; t < 7; t++) acc[q][t] = 0ull;

    for (int ci = 0; ci < 64; ci++) {
#pragma unroll
        for (int j = 0; j < 3; j++) {
            const u64* xr = (j == 0) ? (x0 + ci * 7) : ((j == 1) ? (x1 + ci * 7) : (x2 + ci * 7));
            u64 a[7];
#pragma unroll
            for (int t = 0; t < 7; t++) a[t] = __ldg(xr + t);
#pragma unroll
            for (int q = 0; q < 2; q++) {
                float w = sW[(j * 64 + ci) * 64 + p + q * 32];
                u64 wd = pk2(w, w);
#pragma unroll
                for (int t = 0; t < 7; t++)
                    acc[q][t] = fma2(a[t], wd, acc[q][t]);
            }
        }
    }

#pragma unroll
    for (int q = 0; q < 2; q++) {
        int co = p + q * 32;
        float bv = sb[co];
        float* ob = g_t2 + ((long)nb * 64 + co) * T1;
#pragma unroll
        for (int t = 0; t < 7; t++) {
            float2 a = upk2(acc[q][t]);
            float vx = a.x + bv, vy = a.y + bv;
            vx = (vx > 0.f) ? vx : 0.f;
            vy = (vy > 0.f) ? vy : 0.f;
            *(float2*)(ob + 2 * t) = make_float2(vx, vy);
        }
    }
}

// ---------------- BN (channel axis = node) + final transpose -----------------
// t3 layout: (nb, c, t12); per node n the blob = nb 2n..2n+1 = 1536 contiguous
__global__ void k_bn(const float* __restrict__ gamma, const float* __restrict__ beta,
                     float* __restrict__ out)
{
    int n = blockIdx.x;
    const float* tp = g_t3 + (long)n * (BB * 64 * T2);
    float s = 0.f, s2 = 0.f;
    for (int i = threadIdx.x; i < BB * 64 * T2; i += 256) {
        float v = tp[i]; s += v; s2 += v * v;
    }
    __shared__ float rs[8], rs2[8];
    for (int o = 16; o; o >>= 1) {
        s  += __shfl_down_sync(0xffffffff, s,  o);
        s2 += __shfl_down_sync(0xffffffff, s2, o);
    }
    int lane = threadIdx.x & 31, wid = threadIdx.x >> 5;
    if (lane == 0) { rs[wid] = s; rs2[wid] = s2; }
    __syncthreads();
    __shared__ float smu, srstd;
    if (wid == 0) {
        float a  = (lane < 8) ? rs[lane]  : 0.f;
        float a2 = (lane < 8) ? rs2[lane] : 0.f;
        for (int o = 4; o; o >>= 1) {
            a  += __shfl_down_sync(0xffffffff, a,  o);
            a2 += __shfl_down_sync(0xffffffff, a2, o);
        }
        if (lane == 0) {
            float mu  = a / 1536.f;
            float var = a2 / 1536.f - mu * mu;
            smu = mu; srstd = rsqrtf(var + 1e-5f);
        }
    }
    __syncthreads();
    float mu = smu, rstd = srstd;
    float ga = gamma[n], be = beta[n];
    for (int i = threadIdx.x; i < BB * 64 * T2; i += 256) {
        float v = (tp[i] - mu) * rstd * ga + be;
        int b = i / (64 * T2);
        int r = i % (64 * T2);
        int c = r / T2;
        int t = r % T2;
        out[(((long)b * T2 + t) * NN + n) * 64 + c] = v;
    }
}

// ---------------- launch -----------------------------------------------------
extern "C" void kernel_launch(void* const* d_in, const int* in_sizes, int n_in,
                              void* d_out, int out_size)
{
    const float* X    = (const float*)d_in[0];
    const int*   ei   = (const int*)  d_in[1];
    const float* ew   = (const float*)d_in[2];
    const float* t1w1 = (const float*)d_in[3];
    const float* t1b1 = (const float*)d_in[4];
    const float* t1w2 = (const float*)d_in[5];
    const float* t1b2 = (const float*)d_in[6];
    const float* t1w3 = (const float*)d_in[7];
    const float* t1b3 = (const float*)d_in[8];
    const float* chw  = (const float*)d_in[9];
    const float* chb  = (const float*)d_in[10];
    const float* t2w1 = (const float*)d_in[11];
    const float* t2b1 = (const float*)d_in[12];
    const float* t2w2 = (const float*)d_in[13];
    const float* t2b2 = (const float*)d_in[14];
    const float* t2w3 = (const float*)d_in[15];
    const float* t2b3 = (const float*)d_in[16];
    const float* gam  = (const float*)d_in[17];
    const float* bet  = (const float*)d_in[18];
    float* out = (float*)d_out;

    void *p_t1, *p_t2, *p_t3, *p_tx1, *p_tx2;
    cudaGetSymbolAddress(&p_t1,  g_t1);
    cudaGetSymbolAddress(&p_t2,  g_t2);
    cudaGetSymbolAddress(&p_t3,  g_t3);
    cudaGetSymbolAddress(&p_tx1, g_tx1);
    cudaGetSymbolAddress(&p_tx2, g_tx2);

    const int smemT = 3 * 32 * 3 * 32 * 8;        // 73728 (one ci-phase)
    const int smemC = (3 * 64 * 64 + 64) * 4;     // 49408
    cudaFuncSetAttribute(k_tconv<CI1, TT, 32>, cudaFuncAttributeMaxDynamicSharedMemorySize, smemT);
    cudaFuncSetAttribute(k_tconv<CHH, T1, 32>, cudaFuncAttributeMaxDynamicSharedMemorySize, smemT);
    cudaFuncSetAttribute(k_cheb,               cudaFuncAttributeMaxDynamicSharedMemorySize, smemC);

    const int gridT = (NB_TOTAL + 5) / 6;  // 683

    // preprocessing (order keeps tconv1 at launch slot 4 for the profiler)
    k_zero   <<<(NN + 255) / 256, 256>>>();
    k_deg    <<<EE / 256, 256>>>(ei, ew);
    k_scandis<<<1, 1024>>>();

    // tconv1: X (b,t,n,ci) -> g_t1 (nb, c, t14)
    k_tconv<CI1, TT, 32><<<gridT, 384, smemT>>>(
        X, (long)TT * NN * CI1, (long)CI1, 1L, (long)NN * CI1,
        t1w1, t1b1, t1w2, t1b2, t1w3, t1b3, (float*)p_t1);

    k_scatter<<<EE / 256, 256>>>(ei, ew);

    // Cheb propagation
    k_prop<<<NN, F14>>>((const float4*)p_t1,  (float4*)p_tx1, (const float4*)p_t1, 0);
    k_prop<<<NN, F14>>>((const float4*)p_tx1, (float4*)p_tx2, (const float4*)p_t1, 1);

    // fused Cheb GEMM + bias + relu -> g_t2 (nb, c, t14)
    k_cheb<<<NB_TOTAL / 16, 512, smemC>>>(chw, chb);

    // tconv2: g_t2 (nb, c, t14) -> g_t3 (nb, c, t12); two ci phases
    k_tconv<CHH, T1, 32><<<gridT, 384, smemT>>>(
        (const float*)p_t2, (long)64 * T1, (long)2 * 64 * T1, (long)T1, 1L,
        t2w1, t2b1, t2w2, t2b2, t2w3, t2b3, (float*)p_t3);

    // BN per node + transpose to (B, T2, N, CO)
    k_bn<<<NN, 256>>>(gam, bet, out);
}

// round 4
// speedup vs baseline: 1.0170x; 1.0170x over previous
#include <cuda_runtime.h>
#include <math.h>

#define BB   2
#define TT   16
#define NN   2048
#define CI1  32
#define CHH  64
#define EE   32768
#define T1   14
#define T2   12
#define F1   (BB*T1*CHH)
#define F14  (F1/4)
#define NB_TOTAL (NN*BB)

typedef unsigned long long u64;

__device__ __forceinline__ u64 pk2(float lo, float hi) {
    u64 r; asm("mov.b64 %0, {%1, %2};" : "=l"(r) : "f"(lo), "f"(hi)); return r;
}
__device__ __forceinline__ u64 fma2(u64 a, u64 b, u64 c) {
    u64 r; asm("fma.rn.f32x2 %0, %1, %2, %3;" : "=l"(r) : "l"(a), "l"(b), "l"(c)); return r;
}
__device__ __forceinline__ float2 upk2(u64 a) {
    float2 f; asm("mov.b64 {%0, %1}, %2;" : "=f"(f.x), "=f"(f.y) : "l"(a)); return f;
}

// ---------------- scratch: layout (nb, t, c), c contiguous -------------------
__device__ __align__(16) float g_t1 [NB_TOTAL*T1*CHH];
__device__ __align__(16) float g_tx1[NB_TOTAL*T1*CHH];
__device__ __align__(16) float g_tx2[NB_TOTAL*T1*CHH];
__device__ __align__(16) float g_t2 [NB_TOTAL*T1*CHH];
__device__ __align__(16) float g_t3 [NB_TOTAL*T2*CHH];
__device__ float g_deg[NN];
__device__ float g_dis[NN];
__device__ int   g_rowcount[NN];
__device__ int   g_rowstart[NN+1];
__device__ int   g_cursor[NN];
__device__ int   g_ccol[EE];
__device__ float g_cnorm[EE];

// ---------------- graph preprocessing ---------------------------------------
__global__ void k_zero() {
    int i = blockIdx.x * blockDim.x + threadIdx.x;
    if (i < NN) { g_deg[i] = 0.f; g_rowcount[i] = 0; g_cursor[i] = 0; }
}

__global__ void k_deg(const int* __restrict__ ei, const float* __restrict__ ew) {
    int e = blockIdx.x * blockDim.x + threadIdx.x;
    if (e < EE) {
        int r = ei[e], c = ei[EE + e];
        float w = (r == c) ? 0.f : ew[e];
        atomicAdd(&g_deg[r], w);
        atomicAdd(&g_rowcount[r], 1);
    }
}

__global__ void k_scandis() {
    int tid = threadIdx.x;
    for (int i = tid; i < NN; i += 1024) {
        float d = g_deg[i];
        g_dis[i] = (d > 0.f) ? rsqrtf(d) : 0.f;
    }
    int v0 = g_rowcount[2 * tid], v1 = g_rowcount[2 * tid + 1];
    int s  = v0 + v1;
    int lane = tid & 31, wid = tid >> 5;
    int sc = s;
#pragma unroll
    for (int o = 1; o < 32; o <<= 1) {
        int t = __shfl_up_sync(0xffffffffu, sc, o);
        if (lane >= o) sc += t;
    }
    __shared__ int ws[32];
    if (lane == 31) ws[wid] = sc;
    __syncthreads();
    if (wid == 0) {
        int w = ws[lane];
#pragma unroll
        for (int o = 1; o < 32; o <<= 1) {
            int t = __shfl_up_sync(0xffffffffu, w, o);
            if (lane >= o) w += t;
        }
        ws[lane] = w;
    }
    __syncthreads();
    int base = ((wid > 0) ? ws[wid - 1] : 0) + sc - s;
    g_rowstart[2 * tid + 1] = base + v0;
    g_rowstart[2 * tid + 2] = base + v0 + v1;
    if (tid == 0) g_rowstart[0] = 0;
}

__global__ void k_scatter(const int* __restrict__ ei, const float* __restrict__ ew) {
    int e = blockIdx.x * blockDim.x + threadIdx.x;
    if (e < EE) {
        int r = ei[e], c = ei[EE + e];
        float w = (r == c) ? 0.f : ew[e];
        int pos = g_rowstart[r] + atomicAdd(&g_cursor[r], 1);
        g_ccol[pos]  = c;
        g_cnorm[pos] = -g_dis[r] * w * g_dis[c];
    }
}

// ---------------- gated temporal conv ---------------------------------------
// 384 threads = 6 nb-tiles x (2 t-halves x 32 co-pair lanes), 2 blocks/SM.
// x staged in smem as duplicated f32x2 (u64); weights staged in CIPH phases.
// Inner loop: LDS.64 broadcast x, LDS.64 weights, fma2 only — no LDG, no movs.
template<int CI, int TIN, int CIPH>
__global__ void __launch_bounds__(384, 2) k_tconv(
    const float* __restrict__ x, long sb, long sn, long st,
    const float* __restrict__ w1, const float* __restrict__ bb1,
    const float* __restrict__ w2, const float* __restrict__ bb2,
    const float* __restrict__ w3, const float* __restrict__ bb3,
    float* __restrict__ out)
{
    constexpr int TOUT = TIN - 2;
    constexpr int TH   = TOUT / 2;
    constexpr int NX   = TH + 2;
    constexpr int NPH  = CI / CIPH;
    constexpr int WSZ  = 3 * CIPH * 3 * 32;          // u64 weight slots per phase

    extern __shared__ u64 sm[];
    u64* sw  = sm;          // [3][CIPH][3][32] packed co-pairs
    u64* sxd = sm + WSZ;    // [6][TIN][CI] duplicated x

    // ---- stage x (float4 coalesced LDG -> duplicated u64 in smem) ----
    {
        constexpr int NV = 6 * TIN * (CI / 4);
        for (int idx = threadIdx.x; idx < NV; idx += 384) {
            int ci4 = idx % (CI / 4);
            int rest = idx / (CI / 4);
            int ti = rest % TIN;
            int gg = rest / TIN;
            int nb2 = blockIdx.x * 6 + gg;
            float4 v = make_float4(0.f, 0.f, 0.f, 0.f);
            if (nb2 < NB_TOTAL)
                v = *(const float4*)(x + (long)(nb2 & 1) * sb + (long)(nb2 >> 1) * sn
                                       + (long)ti * st + ci4 * 4);
            u64* dst = sxd + ((gg * TIN + ti) * CI + ci4 * 4);
            dst[0] = pk2(v.x, v.x);
            dst[1] = pk2(v.y, v.y);
            dst[2] = pk2(v.z, v.z);
            dst[3] = pk2(v.w, v.w);
        }
    }

    int p  = threadIdx.x & 31;
    int h  = (threadIdx.x >> 5) & 1;
    int g  = threadIdx.x >> 6;
    int nb = blockIdx.x * 6 + g;
    bool active = (nb < NB_TOTAL);

    u64 acc[3][TH];
#pragma unroll
    for (int j = 0; j < 3; j++)
#pragma unroll
        for (int t = 0; t < TH; t++) acc[j][t] = 0ull;

    const u64* xbase = sxd + (g * TIN + h * TH) * CI;

    for (int ph = 0; ph < NPH; ph++) {
        if (ph > 0) __syncthreads();
        int ci0 = ph * CIPH;
        for (int idx = threadIdx.x; idx < WSZ; idx += 384) {
            int pp = idx & 31;
            int rest = idx >> 5;
            int k = rest % 3; rest /= 3;
            int ci = rest % CIPH;
            int j  = rest / CIPH;
            const float* wj = (j == 0) ? w1 : ((j == 1) ? w2 : w3);
            sw[idx] = pk2(wj[((2 * pp)     * CI + ci0 + ci) * 3 + k],
                          wj[((2 * pp + 1) * CI + ci0 + ci) * 3 + k]);
        }
        __syncthreads();

        if (active) {
            for (int ci = 0; ci < CIPH; ci++) {
                const u64* xr = xbase + (ci0 + ci);
                u64 xx[NX];
#pragma unroll
                for (int i = 0; i < NX; i++) xx[i] = xr[i * CI];  // LDS.64 broadcast
#pragma unroll
                for (int j = 0; j < 3; j++) {
                    u64 wk0 = sw[((j * CIPH + ci) * 3 + 0) * 32 + p];
                    u64 wk1 = sw[((j * CIPH + ci) * 3 + 1) * 32 + p];
                    u64 wk2 = sw[((j * CIPH + ci) * 3 + 2) * 32 + p];
#pragma unroll
                    for (int to = 0; to < TH; to++) {
                        acc[j][to] = fma2(xx[to],     wk0, acc[j][to]);
                        acc[j][to] = fma2(xx[to + 1], wk1, acc[j][to]);
                        acc[j][to] = fma2(xx[to + 2], wk2, acc[j][to]);
                    }
                }
            }
        }
    }

    if (active) {
        float2 bv1 = __ldg((const float2*)bb1 + p);
        float2 bv2 = __ldg((const float2*)bb2 + p);
        float2 bv3 = __ldg((const float2*)bb3 + p);
        float* ob = out + ((long)nb * TOUT + h * TH) * 64 + 2 * p;
#pragma unroll
        for (int to = 0; to < TH; to++) {
            float2 a1 = upk2(acc[0][to]);
            float2 a2 = upk2(acc[1][to]);
            float2 a3 = upk2(acc[2][to]);
            float zx = a2.x + bv2.x, zy = a2.y + bv2.y;
            float sx = __fdividef(1.f, 1.f + __expf(-zx));
            float sy = __fdividef(1.f, 1.f + __expf(-zy));
            float vx = a1.x + bv1.x + sx + a3.x + bv3.x;
            float vy = a1.y + bv1.y + sy + a3.y + bv3.y;
            vx = (vx > 0.f) ? vx : 0.f;
            vy = (vy > 0.f) ? vy : 0.f;
            *(float2*)(ob + to * 64) = make_float2(vx, vy);
        }
    }
}

// ---------------- ChebConv propagation (CSR gather) --------------------------
__global__ void k_prop(const float4* __restrict__ z, float4* __restrict__ out,
                       const float4* __restrict__ x0, int mode)
{
    int n = blockIdx.x;
    int tid = threadIdx.x;
    int e0 = g_rowstart[n], e1 = g_rowstart[n + 1];
    float4 acc = make_float4(0.f, 0.f, 0.f, 0.f);
    for (int e = e0; e < e1; e++) {
        int   c  = __ldg(&g_ccol[e]);
        float nm = __ldg(&g_cnorm[e]);
        float4 v = __ldg(&z[(long)c * F14 + tid]);
        acc.x += nm * v.x; acc.y += nm * v.y;
        acc.z += nm * v.z; acc.w += nm * v.w;
    }
    if (mode) {
        float4 v0 = __ldg(&x0[(long)n * F14 + tid]);
        acc.x = 2.f * acc.x - v0.x; acc.y = 2.f * acc.y - v0.y;
        acc.z = 2.f * acc.z - v0.z; acc.w = 2.f * acc.w - v0.w;
    }
    out[(long)n * F14 + tid] = acc;
}

// ---------------- fused Cheb GEMM (R2 structure, (nb,t,c) layout) ------------
__global__ void __launch_bounds__(448) k_cheb(const float* __restrict__ W,
                                              const float* __restrict__ bias)
{
    extern __shared__ char smraw[];
    u64* sW = (u64*)smraw;  // [3][64][32] packed co pairs
    for (int idx = threadIdx.x; idx < 3 * 64 * 32; idx += 448) {
        int p = idx & 31;
        int jc = idx >> 5;
        sW[idx] = pk2(W[jc * 64 + 2 * p], W[jc * 64 + 2 * p + 1]);
    }
    __syncthreads();

    int p  = threadIdx.x & 31;
    int g  = threadIdx.x >> 5;
    int nb = blockIdx.x * 14 + g;
    if (nb >= NB_TOTAL) return;

    const float4* x0 = (const float4*)(g_t1  + (long)nb * T1 * 64);
    const float4* x1 = (const float4*)(g_tx1 + (long)nb * T1 * 64);
    const float4* x2 = (const float4*)(g_tx2 + (long)nb * T1 * 64);

    u64 acc[T1];
#pragma unroll
    for (int t = 0; t < T1; t++) acc[t] = 0ull;

#pragma unroll
    for (int c4 = 0; c4 < 16; c4++) {
        u64 w0[4], w1[4], w2[4];
#pragma unroll
        for (int u = 0; u < 4; u++) {
            int c = c4 * 4 + u;
            w0[u] = sW[(0 * 64 + c) * 32 + p];
            w1[u] = sW[(1 * 64 + c) * 32 + p];
            w2[u] = sW[(2 * 64 + c) * 32 + p];
        }
#pragma unroll
        for (int t = 0; t < T1; t++) {
            float4 v0 = __ldg(&x0[t * 16 + c4]);
            float4 v1 = __ldg(&x1[t * 16 + c4]);
            float4 v2 = __ldg(&x2[t * 16 + c4]);
            u64 a = acc[t];
            a = fma2(pk2(v0.x, v0.x), w0[0], a);
            a = fma2(pk2(v0.y, v0.y), w0[1], a);
            a = fma2(pk2(v0.z, v0.z), w0[2], a);
            a = fma2(pk2(v0.w, v0.w), w0[3], a);
            a = fma2(pk2(v1.x, v1.x), w1[0], a);
            a = fma2(pk2(v1.y, v1.y), w1[1], a);
            a = fma2(pk2(v1.z, v1.z), w1[2], a);
            a = fma2(pk2(v1.w, v1.w), w1[3], a);
            a = fma2(pk2(v2.x, v2.x), w2[0], a);
            a = fma2(pk2(v2.y, v2.y), w2[1], a);
            a = fma2(pk2(v2.z, v2.z), w2[2], a);
            a = fma2(pk2(v2.w, v2.w), w2[3], a);
            acc[t] = a;
        }
    }

    float2 bv = __ldg((const float2*)bias + p);
    float* ob = g_t2 + (long)nb * T1 * 64 + 2 * p;
#pragma unroll
    for (int t = 0; t < T1; t++) {
        float2 a = upk2(acc[t]);
        float vx = a.x + bv.x, vy = a.y + bv.y;
        vx = (vx > 0.f) ? vx : 0.f;
        vy = (vy > 0.f) ? vy : 0.f;
        *(float2*)(ob + t * 64) = make_float2(vx, vy);
    }
}

// ---------------- BN (channel axis = node) + final transpose -----------------
__global__ void k_bn(const float* __restrict__ gamma, const float* __restrict__ beta,
                     float* __restrict__ out)
{
    int n = blockIdx.x;
    const float* tp = g_t3 + (long)n * (BB * T2 * 64);
    float s = 0.f, s2 = 0.f;
    for (int i = threadIdx.x; i < BB * T2 * 64; i += 256) {
        float v = tp[i]; s += v; s2 += v * v;
    }
    __shared__ float rs[8], rs2[8];
    for (int o = 16; o; o >>= 1) {
        s  += __shfl_down_sync(0xffffffff, s,  o);
        s2 += __shfl_down_sync(0xffffffff, s2, o);
    }
    int lane = threadIdx.x & 31, wid = threadIdx.x >> 5;
    if (lane == 0) { rs[wid] = s; rs2[wid] = s2; }
    __syncthreads();
    __shared__ float smu, srstd;
    if (wid == 0) {
        float a  = (lane < 8) ? rs[lane]  : 0.f;
        float a2 = (lane < 8) ? rs2[lane] : 0.f;
        for (int o = 4; o; o >>= 1) {
            a  += __shfl_down_sync(0xffffffff, a,  o);
            a2 += __shfl_down_sync(0xffffffff, a2, o);
        }
        if (lane == 0) {
            float mu  = a / 1536.f;
            float var = a2 / 1536.f - mu * mu;
            smu = mu; srstd = rsqrtf(var + 1e-5f);
        }
    }
    __syncthreads();
    float mu = smu, rstd = srstd;
    float ga = gamma[n], be = beta[n];
    for (int i = threadIdx.x; i < BB * T2 * 64; i += 256) {
        float v = (tp[i] - mu) * rstd * ga + be;
        int c = i & 63;
        int t = (i >> 6) % T2;
        int b = i / (T2 * 64);
        out[(((long)b * T2 + t) * NN + n) * 64 + c] = v;
    }
}

// ---------------- launch -----------------------------------------------------
extern "C" void kernel_launch(void* const* d_in, const int* in_sizes, int n_in,
                              void* d_out, int out_size)
{
    const float* X    = (const float*)d_in[0];
    const int*   ei   = (const int*)  d_in[1];
    const float* ew   = (const float*)d_in[2];
    const float* t1w1 = (const float*)d_in[3];
    const float* t1b1 = (const float*)d_in[4];
    const float* t1w2 = (const float*)d_in[5];
    const float* t1b2 = (const float*)d_in[6];
    const float* t1w3 = (const float*)d_in[7];
    const float* t1b3 = (const float*)d_in[8];
    const float* chw  = (const float*)d_in[9];
    const float* chb  = (const float*)d_in[10];
    const float* t2w1 = (const float*)d_in[11];
    const float* t2b1 = (const float*)d_in[12];
    const float* t2w2 = (const float*)d_in[13];
    const float* t2b2 = (const float*)d_in[14];
    const float* t2w3 = (const float*)d_in[15];
    const float* t2b3 = (const float*)d_in[16];
    const float* gam  = (const float*)d_in[17];
    const float* bet  = (const float*)d_in[18];
    float* out = (float*)d_out;

    void *p_t1, *p_t2, *p_t3, *p_tx1, *p_tx2;
    cudaGetSymbolAddress(&p_t1,  g_t1);
    cudaGetSymbolAddress(&p_t2,  g_t2);
    cudaGetSymbolAddress(&p_t3,  g_t3);
    cudaGetSymbolAddress(&p_tx1, g_tx1);
    cudaGetSymbolAddress(&p_tx2, g_tx2);

    // smem: weights phase (3*16*3*32 u64 = 36864B) + duplicated x
    const int smemT1 = 36864 + 6 * TT * CI1 * 8;  // 36864 + 24576 = 61440
    const int smemT2 = 36864 + 6 * T1 * CHH * 8;  // 36864 + 43008 = 79872
    const int smemC  = 3 * 64 * 32 * 8;           // 49152
    cudaFuncSetAttribute(k_tconv<CI1, TT, 16>, cudaFuncAttributeMaxDynamicSharedMemorySize, smemT1);
    cudaFuncSetAttribute(k_tconv<CHH, T1, 16>, cudaFuncAttributeMaxDynamicSharedMemorySize, smemT2);
    cudaFuncSetAttribute(k_cheb,               cudaFuncAttributeMaxDynamicSharedMemorySize, smemC);

    const int gridT = (NB_TOTAL + 5) / 6;   // 683
    const int gridC = (NB_TOTAL + 13) / 14; // 293

    k_zero   <<<(NN + 255) / 256, 256>>>();
    k_deg    <<<EE / 256, 256>>>(ei, ew);
    k_scandis<<<1, 1024>>>();
    k_scatter<<<EE / 256, 256>>>(ei, ew);

    // tconv1: X (b,t,n,ci), element (nb,ti,ci) at b*sb + n*sn + ti*st + ci
    k_tconv<CI1, TT, 16><<<gridT, 384, smemT1>>>(
        X, (long)TT * NN * CI1, (long)CI1, (long)NN * CI1,
        t1w1, t1b1, t1w2, t1b2, t1w3, t1b3, (float*)p_t1);

    // Cheb propagation (per-node 1792-float blobs)
    k_prop<<<NN, F14>>>((const float4*)p_t1,  (float4*)p_tx1, (const float4*)p_t1, 0);
    k_prop<<<NN, F14>>>((const float4*)p_tx1, (float4*)p_tx2, (const float4*)p_t1, 1);

    // fused Cheb GEMM + bias + relu -> g_t2 (nb,t,c)
    k_cheb<<<gridC, 448, smemC>>>(chw, chb);

    // tconv2: g_t2 (nb,t,c): element at b*(T1*64) + n*(2*T1*64) + ti*64 + ci
    k_tconv<CHH, T1, 16><<<gridT, 384, smemT2>>>(
        (const float*)p_t2, (long)T1 * 64, (long)2 * T1 * 64, 64L,
        t2w1, t2b1, t2w2, t2b2, t2w3, t2b3, (float*)p_t3);

    // BN per node + transpose to (B, T2, N, CO)
    k_bn<<<NN, 256>>>(gam, bet, out);
}

// round 5
// speedup vs baseline: 1.1405x; 1.1215x over previous
#include <cuda_runtime.h>
#include <math.h>

#define BB   2
#define TT   16
#define NN   2048
#define CI1  32
#define CHH  64
#define EE   32768
#define T1   14
#define T2   12
#define F1   (BB*T1*CHH)
#define F14  (F1/4)
#define NB_TOTAL (NN*BB)

typedef unsigned long long u64;

__device__ __forceinline__ u64 pk2(float lo, float hi) {
    u64 r; asm("mov.b64 %0, {%1, %2};" : "=l"(r) : "f"(lo), "f"(hi)); return r;
}
__device__ __forceinline__ u64 fma2(u64 a, u64 b, u64 c) {
    u64 r; asm("fma.rn.f32x2 %0, %1, %2, %3;" : "=l"(r) : "l"(a), "l"(b), "l"(c)); return r;
}
__device__ __forceinline__ float2 upk2(u64 a) {
    float2 f; asm("mov.b64 {%0, %1}, %2;" : "=f"(f.x), "=f"(f.y) : "l"(a)); return f;
}

// ---------------- scratch: layout (nb, t, c), c contiguous -------------------
__device__ __align__(16) float g_t1 [NB_TOTAL*T1*CHH];
__device__ __align__(16) float g_tx1[NB_TOTAL*T1*CHH];
__device__ __align__(16) float g_tx2[NB_TOTAL*T1*CHH];
__device__ __align__(16) float g_t2 [NB_TOTAL*T1*CHH];
__device__ __align__(16) float g_t3 [NB_TOTAL*T2*CHH];
__device__ float g_deg[NN];
__device__ float g_dis[NN];
__device__ int   g_rowcount[NN];
__device__ int   g_rowstart[NN+1];
__device__ int   g_cursor[NN];
__device__ int   g_ccol[EE];
__device__ float g_cnorm[EE];

// ---------------- graph preprocessing ---------------------------------------
__global__ void k_zero() {
    int i = blockIdx.x * blockDim.x + threadIdx.x;
    if (i < NN) { g_deg[i] = 0.f; g_rowcount[i] = 0; g_cursor[i] = 0; }
}

__global__ void k_deg(const int* __restrict__ ei, const float* __restrict__ ew) {
    int e = blockIdx.x * blockDim.x + threadIdx.x;
    if (e < EE) {
        int r = ei[e], c = ei[EE + e];
        float w = (r == c) ? 0.f : ew[e];
        atomicAdd(&g_deg[r], w);
        atomicAdd(&g_rowcount[r], 1);
    }
}

__global__ void k_scandis() {
    int tid = threadIdx.x;
    for (int i = tid; i < NN; i += 1024) {
        float d = g_deg[i];
        g_dis[i] = (d > 0.f) ? rsqrtf(d) : 0.f;
    }
    int v0 = g_rowcount[2 * tid], v1 = g_rowcount[2 * tid + 1];
    int s  = v0 + v1;
    int lane = tid & 31, wid = tid >> 5;
    int sc = s;
#pragma unroll
    for (int o = 1; o < 32; o <<= 1) {
        int t = __shfl_up_sync(0xffffffffu, sc, o);
        if (lane >= o) sc += t;
    }
    __shared__ int ws[32];
    if (lane == 31) ws[wid] = sc;
    __syncthreads();
    if (wid == 0) {
        int w = ws[lane];
#pragma unroll
        for (int o = 1; o < 32; o <<= 1) {
            int t = __shfl_up_sync(0xffffffffu, w, o);
            if (lane >= o) w += t;
        }
        ws[lane] = w;
    }
    __syncthreads();
    int base = ((wid > 0) ? ws[wid - 1] : 0) + sc - s;
    g_rowstart[2 * tid + 1] = base + v0;
    g_rowstart[2 * tid + 2] = base + v0 + v1;
    if (tid == 0) g_rowstart[0] = 0;
}

__global__ void k_scatter(const int* __restrict__ ei, const float* __restrict__ ew) {
    int e = blockIdx.x * blockDim.x + threadIdx.x;
    if (e < EE) {
        int r = ei[e], c = ei[EE + e];
        float w = (r == c) ? 0.f : ew[e];
        int pos = g_rowstart[r] + atomicAdd(&g_cursor[r], 1);
        g_ccol[pos]  = c;
        g_cnorm[pos] = -g_dis[r] * w * g_dis[c];
    }
}

// ---------------- gated temporal conv ---------------------------------------
// 512 threads = 8 nb-tiles x (2 t-halves x 32 co-pair lanes); grid exact.
// Full weights in smem (u64 co-pairs) + x staged as plain floats in smem.
// Mainloop: 9 LDS.32 + 9 pk2 + 9 LDS.64 + 63 fma2 per ci — no LDG, no sync.
// 1 block/SM (smem), 16 warps, regs ~100 (no spills; cap 128 via bounds 512,1).
template<int CI, int TIN>
__global__ void __launch_bounds__(512, 1) k_tconv(
    const float* __restrict__ x, long sb, long sn, long st,
    const float* __restrict__ w1, const float* __restrict__ bb1,
    const float* __restrict__ w2, const float* __restrict__ bb2,
    const float* __restrict__ w3, const float* __restrict__ bb3,
    float* __restrict__ out)
{
    constexpr int TOUT = TIN - 2;
    constexpr int TH   = TOUT / 2;
    constexpr int NX   = TH + 2;
    constexpr int WSZ  = 3 * CI * 3 * 32;   // u64 weight slots

    extern __shared__ char smraw[];
    u64*   sw = (u64*)smraw;                 // [3][CI][3][32]
    float* sx = (float*)(sw + WSZ);          // [8][TIN][CI]

    // stage weights (packed co-pairs)
    for (int idx = threadIdx.x; idx < WSZ; idx += 512) {
        int pp = idx & 31;
        int rest = idx >> 5;
        int k = rest % 3; rest /= 3;
        int ci = rest % CI;
        int j  = rest / CI;
        const float* wj = (j == 0) ? w1 : ((j == 1) ? w2 : w3);
        sw[idx] = pk2(wj[((2 * pp)     * CI + ci) * 3 + k],
                      wj[((2 * pp + 1) * CI + ci) * 3 + k]);
    }
    // stage x (float4 coalesced)
    {
        constexpr int NV = 8 * TIN * (CI / 4);
        for (int idx = threadIdx.x; idx < NV; idx += 512) {
            int ci4 = idx % (CI / 4);
            int rest = idx / (CI / 4);
            int ti = rest % TIN;
            int gg = rest / TIN;
            int nb2 = blockIdx.x * 8 + gg;
            float4 v = *(const float4*)(x + (long)(nb2 & 1) * sb + (long)(nb2 >> 1) * sn
                                          + (long)ti * st + ci4 * 4);
            *(float4*)(sx + (gg * TIN + ti) * CI + ci4 * 4) = v;
        }
    }
    __syncthreads();

    int p  = threadIdx.x & 31;
    int h  = (threadIdx.x >> 5) & 1;
    int g  = threadIdx.x >> 6;
    int nb = blockIdx.x * 8 + g;

    u64 acc[3][TH];
#pragma unroll
    for (int j = 0; j < 3; j++)
#pragma unroll
        for (int t = 0; t < TH; t++) acc[j][t] = 0ull;

    const float* xbase = sx + (g * TIN + h * TH) * CI;

    for (int ci = 0; ci < CI; ci++) {
        u64 xx[NX];
#pragma unroll
        for (int i = 0; i < NX; i++) {
            float xv = xbase[i * CI + ci];   // LDS.32 broadcast
            xx[i] = pk2(xv, xv);
        }
#pragma unroll
        for (int j = 0; j < 3; j++) {
            u64 wk0 = sw[((j * CI + ci) * 3 + 0) * 32 + p];
            u64 wk1 = sw[((j * CI + ci) * 3 + 1) * 32 + p];
            u64 wk2 = sw[((j * CI + ci) * 3 + 2) * 32 + p];
#pragma unroll
            for (int to = 0; to < TH; to++) {
                acc[j][to] = fma2(xx[to],     wk0, acc[j][to]);
                acc[j][to] = fma2(xx[to + 1], wk1, acc[j][to]);
                acc[j][to] = fma2(xx[to + 2], wk2, acc[j][to]);
            }
        }
    }

    float2 bv1 = __ldg((const float2*)bb1 + p);
    float2 bv2 = __ldg((const float2*)bb2 + p);
    float2 bv3 = __ldg((const float2*)bb3 + p);
    float* ob = out + ((long)nb * TOUT + h * TH) * 64 + 2 * p;
#pragma unroll
    for (int to = 0; to < TH; to++) {
        float2 a1 = upk2(acc[0][to]);
        float2 a2 = upk2(acc[1][to]);
        float2 a3 = upk2(acc[2][to]);
        float zx = a2.x + bv2.x, zy = a2.y + bv2.y;
        float sx2 = __fdividef(1.f, 1.f + __expf(-zx));
        float sy2 = __fdividef(1.f, 1.f + __expf(-zy));
        float vx = a1.x + bv1.x + sx2 + a3.x + bv3.x;
        float vy = a1.y + bv1.y + sy2 + a3.y + bv3.y;
        vx = (vx > 0.f) ? vx : 0.f;
        vy = (vy > 0.f) ? vy : 0.f;
        *(float2*)(ob + to * 64) = make_float2(vx, vy);
    }
}

// ---------------- ChebConv propagation (CSR gather) --------------------------
__global__ void k_prop(const float4* __restrict__ z, float4* __restrict__ out,
                       const float4* __restrict__ x0, int mode)
{
    int n = blockIdx.x;
    int tid = threadIdx.x;
    int e0 = g_rowstart[n], e1 = g_rowstart[n + 1];
    float4 acc = make_float4(0.f, 0.f, 0.f, 0.f);
    for (int e = e0; e < e1; e++) {
        int   c  = __ldg(&g_ccol[e]);
        float nm = __ldg(&g_cnorm[e]);
        float4 v = __ldg(&z[(long)c * F14 + tid]);
        acc.x += nm * v.x; acc.y += nm * v.y;
        acc.z += nm * v.z; acc.w += nm * v.w;
    }
    if (mode) {
        float4 v0 = __ldg(&x0[(long)n * F14 + tid]);
        acc.x = 2.f * acc.x - v0.x; acc.y = 2.f * acc.y - v0.y;
        acc.z = 2.f * acc.z - v0.z; acc.w = 2.f * acc.w - v0.w;
    }
    out[(long)n * F14 + tid] = acc;
}

// ---------------- fused Cheb GEMM (proven R2 version) ------------------------
__global__ void __launch_bounds__(448) k_cheb(const float* __restrict__ W,
                                              const float* __restrict__ bias)
{
    extern __shared__ char smraw[];
    u64* sW = (u64*)smraw;  // [3][64][32] packed co pairs
    for (int idx = threadIdx.x; idx < 3 * 64 * 32; idx += 448) {
        int p = idx & 31;
        int jc = idx >> 5;
        sW[idx] = pk2(W[jc * 64 + 2 * p], W[jc * 64 + 2 * p + 1]);
    }
    __syncthreads();

    int p  = threadIdx.x & 31;
    int g  = threadIdx.x >> 5;
    int nb = blockIdx.x * 14 + g;
    if (nb >= NB_TOTAL) return;

    const float4* x0 = (const float4*)(g_t1  + (long)nb * T1 * 64);
    const float4* x1 = (const float4*)(g_tx1 + (long)nb * T1 * 64);
    const float4* x2 = (const float4*)(g_tx2 + (long)nb * T1 * 64);

    u64 acc[T1];
#pragma unroll
    for (int t = 0; t < T1; t++) acc[t] = 0ull;

#pragma unroll
    for (int c4 = 0; c4 < 16; c4++) {
        u64 w0[4], w1[4], w2[4];
#pragma unroll
        for (int u = 0; u < 4; u++) {
            int c = c4 * 4 + u;
            w0[u] = sW[(0 * 64 + c) * 32 + p];
            w1[u] = sW[(1 * 64 + c) * 32 + p];
            w2[u] = sW[(2 * 64 + c) * 32 + p];
        }
#pragma unroll
        for (int t = 0; t < T1; t++) {
            float4 v0 = __ldg(&x0[t * 16 + c4]);
            float4 v1 = __ldg(&x1[t * 16 + c4]);
            float4 v2 = __ldg(&x2[t * 16 + c4]);
            u64 a = acc[t];
            a = fma2(pk2(v0.x, v0.x), w0[0], a);
            a = fma2(pk2(v0.y, v0.y), w0[1], a);
            a = fma2(pk2(v0.z, v0.z), w0[2], a);
            a = fma2(pk2(v0.w, v0.w), w0[3], a);
            a = fma2(pk2(v1.x, v1.x), w1[0], a);
            a = fma2(pk2(v1.y, v1.y), w1[1], a);
            a = fma2(pk2(v1.z, v1.z), w1[2], a);
            a = fma2(pk2(v1.w, v1.w), w1[3], a);
            a = fma2(pk2(v2.x, v2.x), w2[0], a);
            a = fma2(pk2(v2.y, v2.y), w2[1], a);
            a = fma2(pk2(v2.z, v2.z), w2[2], a);
            a = fma2(pk2(v2.w, v2.w), w2[3], a);
            acc[t] = a;
        }
    }

    float2 bv = __ldg((const float2*)bias + p);
    float* ob = g_t2 + (long)nb * T1 * 64 + 2 * p;
#pragma unroll
    for (int t = 0; t < T1; t++) {
        float2 a = upk2(acc[t]);
        float vx = a.x + bv.x, vy = a.y + bv.y;
        vx = (vx > 0.f) ? vx : 0.f;
        vy = (vy > 0.f) ? vy : 0.f;
        *(float2*)(ob + t * 64) = make_float2(vx, vy);
    }
}

// ---------------- BN (channel axis = node) + final transpose -----------------
__global__ void k_bn(const float* __restrict__ gamma, const float* __restrict__ beta,
                     float* __restrict__ out)
{
    int n = blockIdx.x;
    const float* tp = g_t3 + (long)n * (BB * T2 * 64);
    float s = 0.f, s2 = 0.f;
    for (int i = threadIdx.x; i < BB * T2 * 64; i += 256) {
        float v = tp[i]; s += v; s2 += v * v;
    }
    __shared__ float rs[8], rs2[8];
    for (int o = 16; o; o >>= 1) {
        s  += __shfl_down_sync(0xffffffff, s,  o);
        s2 += __shfl_down_sync(0xffffffff, s2, o);
    }
    int lane = threadIdx.x & 31, wid = threadIdx.x >> 5;
    if (lane == 0) { rs[wid] = s; rs2[wid] = s2; }
    __syncthreads();
    __shared__ float smu, srstd;
    if (wid == 0) {
        float a  = (lane < 8) ? rs[lane]  : 0.f;
        float a2 = (lane < 8) ? rs2[lane] : 0.f;
        for (int o = 4; o; o >>= 1) {
            a  += __shfl_down_sync(0xffffffff, a,  o);
            a2 += __shfl_down_sync(0xffffffff, a2, o);
        }
        if (lane == 0) {
            float mu  = a / 1536.f;
            float var = a2 / 1536.f - mu * mu;
            smu = mu; srstd = rsqrtf(var + 1e-5f);
        }
    }
    __syncthreads();
    float mu = smu, rstd = srstd;
    float ga = gamma[n], be = beta[n];
    for (int i = threadIdx.x; i < BB * T2 * 64; i += 256) {
        float v = (tp[i] - mu) * rstd * ga + be;
        int c = i & 63;
        int t = (i >> 6) % T2;
        int b = i / (T2 * 64);
        out[(((long)b * T2 + t) * NN + n) * 64 + c] = v;
    }
}

// ---------------- launch -----------------------------------------------------
extern "C" void kernel_launch(void* const* d_in, const int* in_sizes, int n_in,
                              void* d_out, int out_size)
{
    const float* X    = (const float*)d_in[0];
    const int*   ei   = (const int*)  d_in[1];
    const float* ew   = (const float*)d_in[2];
    const float* t1w1 = (const float*)d_in[3];
    const float* t1b1 = (const float*)d_in[4];
    const float* t1w2 = (const float*)d_in[5];
    const float* t1b2 = (const float*)d_in[6];
    const float* t1w3 = (const float*)d_in[7];
    const float* t1b3 = (const float*)d_in[8];
    const float* chw  = (const float*)d_in[9];
    const float* chb  = (const float*)d_in[10];
    const float* t2w1 = (const float*)d_in[11];
    const float* t2b1 = (const float*)d_in[12];
    const float* t2w2 = (const float*)d_in[13];
    const float* t2b2 = (const float*)d_in[14];
    const float* t2w3 = (const float*)d_in[15];
    const float* t2b3 = (const float*)d_in[16];
    const float* gam  = (const float*)d_in[17];
    const float* bet  = (const float*)d_in[18];
    float* out = (float*)d_out;

    void *p_t1, *p_t2, *p_t3, *p_tx1, *p_tx2;
    cudaGetSymbolAddress(&p_t1,  g_t1);
    cudaGetSymbolAddress(&p_t2,  g_t2);
    cudaGetSymbolAddress(&p_t3,  g_t3);
    cudaGetSymbolAddress(&p_tx1, g_tx1);
    cudaGetSymbolAddress(&p_tx2, g_tx2);

    // smem: weights u64 + staged x floats
    const int smemT1 = 3 * CI1 * 3 * 32 * 8 + 8 * TT * CI1 * 4;  // 73728+16384=90112
    const int smemT2 = 3 * CHH * 3 * 32 * 8 + 8 * T1 * CHH * 4;  // 147456+28672=176128
    const int smemC  = 3 * 64 * 32 * 8;                          // 49152
    cudaFuncSetAttribute(k_tconv<CI1, TT>, cudaFuncAttributeMaxDynamicSharedMemorySize, smemT1);
    cudaFuncSetAttribute(k_tconv<CHH, T1>, cudaFuncAttributeMaxDynamicSharedMemorySize, smemT2);
    cudaFuncSetAttribute(k_cheb,           cudaFuncAttributeMaxDynamicSharedMemorySize, smemC);

    const int gridT = NB_TOTAL / 8;          // 512 (exact)
    const int gridC = (NB_TOTAL + 13) / 14;  // 293

    k_zero   <<<(NN + 255) / 256, 256>>>();          // 0
    k_deg    <<<EE / 256, 256>>>(ei, ew);            // 1
    k_scandis<<<1, 1024>>>();                        // 2

    // 3: tconv1 (profiled slot): X (b,t,n,ci)
    k_tconv<CI1, TT><<<gridT, 512, smemT1>>>(
        X, (long)TT * NN * CI1, (long)CI1, (long)NN * CI1,
        t1w1, t1b1, t1w2, t1b2, t1w3, t1b3, (float*)p_t1);

    k_scatter<<<EE / 256, 256>>>(ei, ew);            // 4

    k_prop<<<NN, F14>>>((const float4*)p_t1,  (float4*)p_tx1, (const float4*)p_t1, 0);  // 5
    k_prop<<<NN, F14>>>((const float4*)p_tx1, (float4*)p_tx2, (const float4*)p_t1, 1);  // 6

    k_cheb<<<gridC, 448, smemC>>>(chw, chb);         // 7

    // 8: tconv2 from g_t2 (nb,t,c)
    k_tconv<CHH, T1><<<gridT, 512, smemT2>>>(
        (const float*)p_t2, (long)T1 * 64, (long)2 * T1 * 64, 64L,
        t2w1, t2b1, t2w2, t2b2, t2w3, t2b3, (float*)p_t3);

    k_bn<<<NN, 256>>>(gam, bet, out);                // 9
}

// round 8
// speedup vs baseline: 1.3965x; 1.2245x over previous
#include <cuda_runtime.h>
#include <cuda_bf16.h>
#include <math.h>
#include <stdint.h>

#define BB   2
#define TT   16
#define NN   2048
#define CI1  32
#define CHH  64
#define EE   32768
#define T1   14
#define T2   12
#define F1   (BB*T1*CHH)
#define F14  (F1/4)
#define NB_TOTAL (NN*BB)

typedef unsigned long long u64;

__device__ __forceinline__ u64 pk2(float lo, float hi) {
    u64 r; asm("mov.b64 %0, {%1, %2};" : "=l"(r) : "f"(lo), "f"(hi)); return r;
}
__device__ __forceinline__ u64 fma2(u64 a, u64 b, u64 c) {
    u64 r; asm("fma.rn.f32x2 %0, %1, %2, %3;" : "=l"(r) : "l"(a), "l"(b), "l"(c)); return r;
}
__device__ __forceinline__ float2 upk2(u64 a) {
    float2 f; asm("mov.b64 {%0, %1}, %2;" : "=f"(f.x), "=f"(f.y) : "l"(a)); return f;
}
__device__ __forceinline__ uint32_t pkbf2(float a, float b) {
    __nv_bfloat162 h = __floats2bfloat162_rn(a, b);
    return *reinterpret_cast<uint32_t*>(&h);
}
// mma.sync m16n8k16 bf16 (HMMA; supported on base sm_103 target)
__device__ __forceinline__ void mma_bf16(float* d, const uint32_t* a,
                                         uint32_t b0, uint32_t b1) {
    asm volatile(
        "mma.sync.aligned.m16n8k16.row.col.f32.bf16.bf16.f32 "
        "{%0,%1,%2,%3}, {%4,%5,%6,%7}, {%8,%9}, {%0,%1,%2,%3};"
        : "+f"(d[0]), "+f"(d[1]), "+f"(d[2]), "+f"(d[3])
        : "r"(a[0]), "r"(a[1]), "r"(a[2]), "r"(a[3]), "r"(b0), "r"(b1));
}

// ---------------- scratch: layout (nb, t, c), c contiguous -------------------
__device__ __align__(16) float g_t1 [NB_TOTAL*T1*CHH];
__device__ __align__(16) float g_tx1[NB_TOTAL*T1*CHH];
__device__ __align__(16) float g_tx2[NB_TOTAL*T1*CHH];
__device__ __align__(16) float g_t2 [NB_TOTAL*T1*CHH];
__device__ __align__(16) float g_t3 [NB_TOTAL*T2*CHH];
__device__ float g_deg[NN];
__device__ float g_dis[NN];
__device__ int   g_rowcount[NN];
__device__ int   g_rowstart[NN+1];
__device__ int   g_cursor[NN];
__device__ int   g_ccol[EE];
__device__ float g_cnorm[EE];
// prepped bf16 split weights for tconv2 MMA: [3 kc][192 n][64 k]
__device__ __align__(16) __nv_bfloat16 g_bh[3*192*64];
__device__ __align__(16) __nv_bfloat16 g_bl[3*192*64];

// ---------------- graph preprocessing ---------------------------------------
__global__ void k_zero() {
    int i = blockIdx.x * blockDim.x + threadIdx.x;
    if (i < NN) { g_deg[i] = 0.f; g_rowcount[i] = 0; g_cursor[i] = 0; }
}

__global__ void k_deg(const int* __restrict__ ei, const float* __restrict__ ew) {
    int e = blockIdx.x * blockDim.x + threadIdx.x;
    if (e < EE) {
        int r = ei[e], c = ei[EE + e];
        float w = (r == c) ? 0.f : ew[e];
        atomicAdd(&g_deg[r], w);
        atomicAdd(&g_rowcount[r], 1);
    }
}

__global__ void k_scandis() {
    int tid = threadIdx.x;
    for (int i = tid; i < NN; i += 1024) {
        float d = g_deg[i];
        g_dis[i] = (d > 0.f) ? rsqrtf(d) : 0.f;
    }
    int v0 = g_rowcount[2 * tid], v1 = g_rowcount[2 * tid + 1];
    int s  = v0 + v1;
    int lane = tid & 31, wid = tid >> 5;
    int sc = s;
#pragma unroll
    for (int o = 1; o < 32; o <<= 1) {
        int t = __shfl_up_sync(0xffffffffu, sc, o);
        if (lane >= o) sc += t;
    }
    __shared__ int ws[32];
    if (lane == 31) ws[wid] = sc;
    __syncthreads();
    if (wid == 0) {
        int w = ws[lane];
#pragma unroll
        for (int o = 1; o < 32; o <<= 1) {
            int t = __shfl_up_sync(0xffffffffu, w, o);
            if (lane >= o) w += t;
        }
        ws[lane] = w;
    }
    __syncthreads();
    int base = ((wid > 0) ? ws[wid - 1] : 0) + sc - s;
    g_rowstart[2 * tid + 1] = base + v0;
    g_rowstart[2 * tid + 2] = base + v0 + v1;
    if (tid == 0) g_rowstart[0] = 0;
}

__global__ void k_scatter(const int* __restrict__ ei, const float* __restrict__ ew) {
    int e = blockIdx.x * blockDim.x + threadIdx.x;
    if (e < EE) {
        int r = ei[e], c = ei[EE + e];
        float w = (r == c) ? 0.f : ew[e];
        int pos = g_rowstart[r] + atomicAdd(&g_cursor[r], 1);
        g_ccol[pos]  = c;
        g_cnorm[pos] = -g_dis[r] * w * g_dis[c];
    }
}

// ---------------- weight prep for MMA: fp32 -> bf16 hi/lo --------------------
__global__ void k_wprep(const float* __restrict__ w1, const float* __restrict__ w2,
                        const float* __restrict__ w3) {
    int idx = blockIdx.x * blockDim.x + threadIdx.x;
    if (idx >= 3 * 192 * 64) return;
    int kc = idx / (192 * 64);
    int n  = (idx / 64) % 192;
    int ci = idx % 64;
    int j  = n / 64, co = n % 64;
    const float* wj = (j == 0) ? w1 : ((j == 1) ? w2 : w3);
    float v = wj[(co * 64 + ci) * 3 + kc];
    __nv_bfloat16 h = __float2bfloat16(v);
    float lof = v - __bfloat162float(h);
    g_bh[idx] = h;
    g_bl[idx] = __float2bfloat16(lof);
}

// ---------------- gated temporal conv (scalar, used for tconv1) --------------
template<int CI, int TIN>
__global__ void __launch_bounds__(512, 1) k_tconv(
    const float* __restrict__ x, long sb, long sn, long st,
    const float* __restrict__ w1, const float* __restrict__ bb1,
    const float* __restrict__ w2, const float* __restrict__ bb2,
    const float* __restrict__ w3, const float* __restrict__ bb3,
    float* __restrict__ out)
{
    constexpr int TOUT = TIN - 2;
    constexpr int TH   = TOUT / 2;
    constexpr int NX   = TH + 2;
    constexpr int WSZ  = 3 * CI * 3 * 32;

    extern __shared__ char smraw[];
    u64*   sw = (u64*)smraw;
    float* sx = (float*)(sw + WSZ);

    for (int idx = threadIdx.x; idx < WSZ; idx += 512) {
        int pp = idx & 31;
        int rest = idx >> 5;
        int k = rest % 3; rest /= 3;
        int ci = rest % CI;
        int j  = rest / CI;
        const float* wj = (j == 0) ? w1 : ((j == 1) ? w2 : w3);
        sw[idx] = pk2(wj[((2 * pp)     * CI + ci) * 3 + k],
                      wj[((2 * pp + 1) * CI + ci) * 3 + k]);
    }
    {
        constexpr int NV = 8 * TIN * (CI / 4);
        for (int idx = threadIdx.x; idx < NV; idx += 512) {
            int ci4 = idx % (CI / 4);
            int rest = idx / (CI / 4);
            int ti = rest % TIN;
            int gg = rest / TIN;
            int nb2 = blockIdx.x * 8 + gg;
            float4 v = *(const float4*)(x + (long)(nb2 & 1) * sb + (long)(nb2 >> 1) * sn
                                          + (long)ti * st + ci4 * 4);
            *(float4*)(sx + (gg * TIN + ti) * CI + ci4 * 4) = v;
        }
    }
    __syncthreads();

    int p  = threadIdx.x & 31;
    int h  = (threadIdx.x >> 5) & 1;
    int g  = threadIdx.x >> 6;
    int nb = blockIdx.x * 8 + g;

    u64 acc[3][TH];
#pragma unroll
    for (int j = 0; j < 3; j++)
#pragma unroll
        for (int t = 0; t < TH; t++) acc[j][t] = 0ull;

    const float* xbase = sx + (g * TIN + h * TH) * CI;

    for (int ci = 0; ci < CI; ci++) {
        u64 xx[NX];
#pragma unroll
        for (int i = 0; i < NX; i++) {
            float xv = xbase[i * CI + ci];
            xx[i] = pk2(xv, xv);
        }
#pragma unroll
        for (int j = 0; j < 3; j++) {
            u64 wk0 = sw[((j * CI + ci) * 3 + 0) * 32 + p];
            u64 wk1 = sw[((j * CI + ci) * 3 + 1) * 32 + p];
            u64 wk2 = sw[((j * CI + ci) * 3 + 2) * 32 + p];
#pragma unroll
            for (int to = 0; to < TH; to++) {
                acc[j][to] = fma2(xx[to],     wk0, acc[j][to]);
                acc[j][to] = fma2(xx[to + 1], wk1, acc[j][to]);
                acc[j][to] = fma2(xx[to + 2], wk2, acc[j][to]);
            }
        }
    }

    float2 bv1 = __ldg((const float2*)bb1 + p);
    float2 bv2 = __ldg((const float2*)bb2 + p);
    float2 bv3 = __ldg((const float2*)bb3 + p);
    float* ob = out + ((long)nb * TOUT + h * TH) * 64 + 2 * p;
#pragma unroll
    for (int to = 0; to < TH; to++) {
        float2 a1 = upk2(acc[0][to]);
        float2 a2 = upk2(acc[1][to]);
        float2 a3 = upk2(acc[2][to]);
        float zx = a2.x + bv2.x, zy = a2.y + bv2.y;
        float sx2 = __fdividef(1.f, 1.f + __expf(-zx));
        float sy2 = __fdividef(1.f, 1.f + __expf(-zy));
        float vx = a1.x + bv1.x + sx2 + a3.x + bv3.x;
        float vy = a1.y + bv1.y + sy2 + a3.y + bv3.y;
        vx = (vx > 0.f) ? vx : 0.f;
        vy = (vy > 0.f) ? vy : 0.f;
        *(float2*)(ob + to * 64) = make_float2(vx, vy);
    }
}

// ---------------- tconv2 via mma.sync bf16-split HMMA ------------------------
// GEMM: M = 49152 rows (nb,t), N = 192 (3 gates x 64 co), K = 3 kc x 64.
// D = Ahi*Bhi + Ahi*Blo + Alo*Bhi (bf16 split, fp32 accumulate).
// Block: 256 thr = 8 warps; tile M=128 N=192; warp = M32 x N96.
#define APITCH 72     /* bf16 pitch for staged A (bank-conflict-free frags) */
#define DPITCH 196    /* f32 pitch for D tile */
#define OFF_BIAS2 0
#define OFF_AH   768
#define OFF_AL   (OFF_AH + 128*APITCH*2)   /* +18432 */
#define OFF_D    (OFF_AL + 128*APITCH*2)   /* 37632 */
#define SMEM_H   (OFF_D + 128*DPITCH*4)    /* 37632 + 100352 = 137984 */

__global__ void __launch_bounds__(256, 1) k_tconv2_hmma(
    const float* __restrict__ bb1, const float* __restrict__ bb2,
    const float* __restrict__ bb3)
{
    extern __shared__ char smem[];
    float*         sbias = (float*)(smem + OFF_BIAS2);
    __nv_bfloat16* sAh   = (__nv_bfloat16*)(smem + OFF_AH);
    __nv_bfloat16* sAl   = (__nv_bfloat16*)(smem + OFF_AL);
    float*         sD    = (float*)(smem + OFF_D);

    int tid = threadIdx.x;
    if (tid < 64) {
        sbias[tid]       = bb1[tid];
        sbias[64 + tid]  = bb2[tid];
        sbias[128 + tid] = bb3[tid];
    }

    int lane = tid & 31, w = tid >> 5;
    int m0 = (w & 3) * 32;      // warp M offset in tile
    int n0 = (w >> 2) * 96;     // warp N offset
    int g  = lane >> 2, tg = lane & 3;

    long Rbase = (long)blockIdx.x * 128;

    float acc[2][12][4];
#pragma unroll
    for (int s = 0; s < 2; s++)
#pragma unroll
        for (int nt = 0; nt < 12; nt++)
#pragma unroll
            for (int q = 0; q < 4; q++) acc[s][nt][q] = 0.f;

    int rA = tid >> 1, halfA = tid & 1;
    long RA = Rbase + rA;
    int nbA = (int)(RA / 12), tA = (int)(RA % 12);

    for (int kc = 0; kc < 3; kc++) {
        __syncthreads();
        // ---- stage A: rows -> bf16 hi/lo, padded pitch
        {
            const float4* src = (const float4*)(g_t2 + ((long)nbA * T1 + tA + kc) * 64)
                                + halfA * 8;
            uint2* dh = (uint2*)(sAh + rA * APITCH + halfA * 32);
            uint2* dl = (uint2*)(sAl + rA * APITCH + halfA * 32);
#pragma unroll
            for (int v = 0; v < 8; v++) {
                float4 xv = __ldg(&src[v]);
                float hx = __bfloat162float(__float2bfloat16(xv.x));
                float hy = __bfloat162float(__float2bfloat16(xv.y));
                float hz = __bfloat162float(__float2bfloat16(xv.z));
                float hw = __bfloat162float(__float2bfloat16(xv.w));
                dh[v] = make_uint2(pkbf2(hx, hy), pkbf2(hz, hw));
                dl[v] = make_uint2(pkbf2(xv.x - hx, xv.y - hy),
                                   pkbf2(xv.z - hz, xv.w - hw));
            }
        }
        __syncthreads();

        const __nv_bfloat16* bh = g_bh + (long)kc * 192 * 64;
        const __nv_bfloat16* bl = g_bl + (long)kc * 192 * 64;

#pragma unroll
        for (int ks = 0; ks < 4; ks++) {
            uint32_t ah[2][4], al[2][4];
#pragma unroll
            for (int s = 0; s < 2; s++) {
                int row = m0 + s * 16 + g;
                const __nv_bfloat16* ph = sAh + row * APITCH + ks * 16 + 2 * tg;
                const __nv_bfloat16* pl = sAl + row * APITCH + ks * 16 + 2 * tg;
                ah[s][0] = *(const uint32_t*)(ph);
                ah[s][1] = *(const uint32_t*)(ph + 8 * APITCH);
                ah[s][2] = *(const uint32_t*)(ph + 8);
                ah[s][3] = *(const uint32_t*)(ph + 8 * APITCH + 8);
                al[s][0] = *(const uint32_t*)(pl);
                al[s][1] = *(const uint32_t*)(pl + 8 * APITCH);
                al[s][2] = *(const uint32_t*)(pl + 8);
                al[s][3] = *(const uint32_t*)(pl + 8 * APITCH + 8);
            }
#pragma unroll
            for (int nt = 0; nt < 12; nt++) {
                int n = n0 + nt * 8 + g;
                const uint32_t* pbh = (const uint32_t*)(bh + (long)n * 64 + ks * 16 + 2 * tg);
                const uint32_t* pbl = (const uint32_t*)(bl + (long)n * 64 + ks * 16 + 2 * tg);
                uint32_t b0h = __ldg(pbh), b1h = __ldg(pbh + 4);
                uint32_t b0l = __ldg(pbl), b1l = __ldg(pbl + 4);
#pragma unroll
                for (int s = 0; s < 2; s++) {
                    mma_bf16(acc[s][nt], ah[s], b0h, b1h);
                    mma_bf16(acc[s][nt], ah[s], b0l, b1l);
                    mma_bf16(acc[s][nt], al[s], b0h, b1h);
                }
            }
        }
    }
    __syncthreads();
    // ---- dump accumulators to D tile
#pragma unroll
    for (int s = 0; s < 2; s++)
#pragma unroll
        for (int nt = 0; nt < 12; nt++) {
            int row = m0 + s * 16 + g;
            int col = n0 + nt * 8 + 2 * tg;
            *(float2*)(sD + (long)row * DPITCH + col) =
                make_float2(acc[s][nt][0], acc[s][nt][1]);
            *(float2*)(sD + (long)(row + 8) * DPITCH + col) =
                make_float2(acc[s][nt][2], acc[s][nt][3]);
        }
    __syncthreads();
    // ---- gate + bias + relu epilogue, write (nb,t,c)
    {
        float* orow = g_t3 + ((long)nbA * T2 + tA) * 64;
        const float* drow = sD + (long)rA * DPITCH;
#pragma unroll
        for (int i = 0; i < 32; i++) {
            int co = halfA * 32 + i;
            float a1 = drow[co]        + sbias[co];
            float a2 = drow[64 + co]   + sbias[64 + co];
            float a3 = drow[128 + co]  + sbias[128 + co];
            float sg = __fdividef(1.f, 1.f + __expf(-a2));
            float v  = a1 + sg + a3;
            orow[co] = (v > 0.f) ? v : 0.f;
        }
    }
}

// ---------------- ChebConv propagation (CSR gather) --------------------------
__global__ void k_prop(const float4* __restrict__ z, float4* __restrict__ out,
                       const float4* __restrict__ x0, int mode)
{
    int n = blockIdx.x;
    int tid = threadIdx.x;
    int e0 = g_rowstart[n], e1 = g_rowstart[n + 1];
    float4 acc = make_float4(0.f, 0.f, 0.f, 0.f);
    for (int e = e0; e < e1; e++) {
        int   c  = __ldg(&g_ccol[e]);
        float nm = __ldg(&g_cnorm[e]);
        float4 v = __ldg(&z[(long)c * F14 + tid]);
        acc.x += nm * v.x; acc.y += nm * v.y;
        acc.z += nm * v.z; acc.w += nm * v.w;
    }
    if (mode) {
        float4 v0 = __ldg(&x0[(long)n * F14 + tid]);
        acc.x = 2.f * acc.x - v0.x; acc.y = 2.f * acc.y - v0.y;
        acc.z = 2.f * acc.z - v0.z; acc.w = 2.f * acc.w - v0.w;
    }
    out[(long)n * F14 + tid] = acc;
}

// ---------------- fused Cheb GEMM (proven R2 version) ------------------------
__global__ void __launch_bounds__(448) k_cheb(const float* __restrict__ W,
                                              const float* __restrict__ bias)
{
    extern __shared__ char smraw[];
    u64* sW = (u64*)smraw;
    for (int idx = threadIdx.x; idx < 3 * 64 * 32; idx += 448) {
        int p = idx & 31;
        int jc = idx >> 5;
        sW[idx] = pk2(W[jc * 64 + 2 * p], W[jc * 64 + 2 * p + 1]);
    }
    __syncthreads();

    int p  = threadIdx.x & 31;
    int g  = threadIdx.x >> 5;
    int nb = blockIdx.x * 14 + g;
    if (nb >= NB_TOTAL) return;

    const float4* x0 = (const float4*)(g_t1  + (long)nb * T1 * 64);
    const float4* x1 = (const float4*)(g_tx1 + (long)nb * T1 * 64);
    const float4* x2 = (const float4*)(g_tx2 + (long)nb * T1 * 64);

    u64 acc[T1];
#pragma unroll
    for (int t = 0; t < T1; t++) acc[t] = 0ull;

#pragma unroll
    for (int c4 = 0; c4 < 16; c4++) {
        u64 w0[4], w1[4], w2[4];
#pragma unroll
        for (int u = 0; u < 4; u++) {
            int c = c4 * 4 + u;
            w0[u] = sW[(0 * 64 + c) * 32 + p];
            w1[u] = sW[(1 * 64 + c) * 32 + p];
            w2[u] = sW[(2 * 64 + c) * 32 + p];
        }
#pragma unroll
        for (int t = 0; t < T1; t++) {
            float4 v0 = __ldg(&x0[t * 16 + c4]);
            float4 v1 = __ldg(&x1[t * 16 + c4]);
            float4 v2 = __ldg(&x2[t * 16 + c4]);
            u64 a = acc[t];
            a = fma2(pk2(v0.x, v0.x), w0[0], a);
            a = fma2(pk2(v0.y, v0.y), w0[1], a);
            a = fma2(pk2(v0.z, v0.z), w0[2], a);
            a = fma2(pk2(v0.w, v0.w), w0[3], a);
            a = fma2(pk2(v1.x, v1.x), w1[0], a);
            a = fma2(pk2(v1.y, v1.y), w1[1], a);
            a = fma2(pk2(v1.z, v1.z), w1[2], a);
            a = fma2(pk2(v1.w, v1.w), w1[3], a);
            a = fma2(pk2(v2.x, v2.x), w2[0], a);
            a = fma2(pk2(v2.y, v2.y), w2[1], a);
            a = fma2(pk2(v2.z, v2.z), w2[2], a);
            a = fma2(pk2(v2.w, v2.w), w2[3], a);
            acc[t] = a;
        }
    }

    float2 bv = __ldg((const float2*)bias + p);
    float* ob = g_t2 + (long)nb * T1 * 64 + 2 * p;
#pragma unroll
    for (int t = 0; t < T1; t++) {
        float2 a = upk2(acc[t]);
        float vx = a.x + bv.x, vy = a.y + bv.y;
        vx = (vx > 0.f) ? vx : 0.f;
        vy = (vy > 0.f) ? vy : 0.f;
        *(float2*)(ob + t * 64) = make_float2(vx, vy);
    }
}

// ---------------- BN (channel axis = node) + final transpose -----------------
__global__ void k_bn(const float* __restrict__ gamma, const float* __restrict__ beta,
                     float* __restrict__ out)
{
    int n = blockIdx.x;
    const float* tp = g_t3 + (long)n * (BB * T2 * 64);
    float s = 0.f, s2 = 0.f;
    for (int i = threadIdx.x; i < BB * T2 * 64; i += 256) {
        float v = tp[i]; s += v; s2 += v * v;
    }
    __shared__ float rs[8], rs2[8];
    for (int o = 16; o; o >>= 1) {
        s  += __shfl_down_sync(0xffffffff, s,  o);
        s2 += __shfl_down_sync(0xffffffff, s2, o);
    }
    int lane = threadIdx.x & 31, wid = threadIdx.x >> 5;
    if (lane == 0) { rs[wid] = s; rs2[wid] = s2; }
    __syncthreads();
    __shared__ float smu, srstd;
    if (wid == 0) {
        float a  = (lane < 8) ? rs[lane]  : 0.f;
        float a2 = (lane < 8) ? rs2[lane] : 0.f;
        for (int o = 4; o; o >>= 1) {
            a  += __shfl_down_sync(0xffffffff, a,  o);
            a2 += __shfl_down_sync(0xffffffff, a2, o);
        }
        if (lane == 0) {
            float mu  = a / 1536.f;
            float var = a2 / 1536.f - mu * mu;
            smu = mu; srstd = rsqrtf(var + 1e-5f);
        }
    }
    __syncthreads();
    float mu = smu, rstd = srstd;
    float ga = gamma[n], be = beta[n];
    for (int i = threadIdx.x; i < BB * T2 * 64; i += 256) {
        float v = (tp[i] - mu) * rstd * ga + be;
        int c = i & 63;
        int t = (i >> 6) % T2;
        int b = i / (T2 * 64);
        out[(((long)b * T2 + t) * NN + n) * 64 + c] = v;
    }
}

// ---------------- launch -----------------------------------------------------
extern "C" void kernel_launch(void* const* d_in, const int* in_sizes, int n_in,
                              void* d_out, int out_size)
{
    const float* X    = (const float*)d_in[0];
    const int*   ei   = (const int*)  d_in[1];
    const float* ew   = (const float*)d_in[2];
    const float* t1w1 = (const float*)d_in[3];
    const float* t1b1 = (const float*)d_in[4];
    const float* t1w2 = (const float*)d_in[5];
    const float* t1b2 = (const float*)d_in[6];
    const float* t1w3 = (const float*)d_in[7];
    const float* t1b3 = (const float*)d_in[8];
    const float* chw  = (const float*)d_in[9];
    const float* chb  = (const float*)d_in[10];
    const float* t2w1 = (const float*)d_in[11];
    const float* t2b1 = (const float*)d_in[12];
    const float* t2w2 = (const float*)d_in[13];
    const float* t2b2 = (const float*)d_in[14];
    const float* t2w3 = (const float*)d_in[15];
    const float* t2b3 = (const float*)d_in[16];
    const float* gam  = (const float*)d_in[17];
    const float* bet  = (const float*)d_in[18];
    float* out = (float*)d_out;

    void *p_t1, *p_t2, *p_tx1, *p_tx2;
    cudaGetSymbolAddress(&p_t1,  g_t1);
    cudaGetSymbolAddress(&p_t2,  g_t2);
    cudaGetSymbolAddress(&p_tx1, g_tx1);
    cudaGetSymbolAddress(&p_tx2, g_tx2);

    const int smemT1 = 3 * CI1 * 3 * 32 * 8 + 8 * TT * CI1 * 4;  // 90112
    const int smemC  = 3 * 64 * 32 * 8;                          // 49152
    cudaFuncSetAttribute(k_tconv<CI1, TT>, cudaFuncAttributeMaxDynamicSharedMemorySize, smemT1);
    cudaFuncSetAttribute(k_cheb,           cudaFuncAttributeMaxDynamicSharedMemorySize, smemC);
    cudaFuncSetAttribute(k_tconv2_hmma,    cudaFuncAttributeMaxDynamicSharedMemorySize, SMEM_H);

    const int gridT = NB_TOTAL / 8;          // 512
    const int gridC = (NB_TOTAL + 13) / 14;  // 293

    k_zero   <<<(NN + 255) / 256, 256>>>();
    k_deg    <<<EE / 256, 256>>>(ei, ew);
    k_scandis<<<1, 1024>>>();
    k_wprep  <<<144, 256>>>(t2w1, t2w2, t2w3);

    // tconv1: X (b,t,n,ci)
    k_tconv<CI1, TT><<<gridT, 512, smemT1>>>(
        X, (long)TT * NN * CI1, (long)CI1, (long)NN * CI1,
        t1w1, t1b1, t1w2, t1b2, t1w3, t1b3, (float*)p_t1);

    k_scatter<<<EE / 256, 256>>>(ei, ew);

    k_prop<<<NN, F14>>>((const float4*)p_t1,  (float4*)p_tx1, (const float4*)p_t1, 0);
    k_prop<<<NN, F14>>>((const float4*)p_tx1, (float4*)p_tx2, (const float4*)p_t1, 1);

    k_cheb<<<gridC, 448, smemC>>>(chw, chb);

    // tconv2 via mma.sync HMMA: 384 tiles of 128 (nb,t) rows
    k_tconv2_hmma<<<NB_TOTAL * T2 / 128, 256, SMEM_H>>>(t2b1, t2b2, t2b3);

    k_bn<<<NN, 256>>>(gam, bet, out);
}

// round 9
// speedup vs baseline: 1.9069x; 1.3654x over previous
#include <cuda_runtime.h>
#include <cuda_bf16.h>
#include <math.h>
#include <stdint.h>

#define BB   2
#define TT   16
#define NN   2048
#define CI1  32
#define CHH  64
#define EE   32768
#define T1   14
#define T2   12
#define F1   (BB*T1*CHH)
#define F14  (F1/4)
#define NB_TOTAL (NN*BB)

typedef unsigned long long u64;

__device__ __forceinline__ u64 pk2(float lo, float hi) {
    u64 r; asm("mov.b64 %0, {%1, %2};" : "=l"(r) : "f"(lo), "f"(hi)); return r;
}
__device__ __forceinline__ u64 fma2(u64 a, u64 b, u64 c) {
    u64 r; asm("fma.rn.f32x2 %0, %1, %2, %3;" : "=l"(r) : "l"(a), "l"(b), "l"(c)); return r;
}
__device__ __forceinline__ float2 upk2(u64 a) {
    float2 f; asm("mov.b64 {%0, %1}, %2;" : "=f"(f.x), "=f"(f.y) : "l"(a)); return f;
}
__device__ __forceinline__ uint32_t pkbf2(float a, float b) {
    __nv_bfloat162 h = __floats2bfloat162_rn(a, b);
    return *reinterpret_cast<uint32_t*>(&h);
}
__device__ __forceinline__ void mma_bf16(float* d, const uint32_t* a,
                                         uint32_t b0, uint32_t b1) {
    asm volatile(
        "mma.sync.aligned.m16n8k16.row.col.f32.bf16.bf16.f32 "
        "{%0,%1,%2,%3}, {%4,%5,%6,%7}, {%8,%9}, {%0,%1,%2,%3};"
        : "+f"(d[0]), "+f"(d[1]), "+f"(d[2]), "+f"(d[3])
        : "r"(a[0]), "r"(a[1]), "r"(a[2]), "r"(a[3]), "r"(b0), "r"(b1));
}

// ---------------- scratch ----------------------------------------------------
__device__ __align__(16) float g_t1 [NB_TOTAL*T1*CHH];
__device__ __align__(16) float g_tx1[NB_TOTAL*T1*CHH];
__device__ __align__(16) float g_tx2[NB_TOTAL*T1*CHH];
__device__ __align__(16) float g_t2 [NB_TOTAL*T1*CHH];
__device__ __align__(16) float g_t3 [NB_TOTAL*T2*CHH];
__device__ float g_deg[NN];
__device__ float g_dis[NN];
__device__ int   g_rowcount[NN];
__device__ int   g_rowstart[NN+1];
__device__ int   g_cursor[NN];
__device__ int   g_ccol[EE];
__device__ float g_cnorm[EE];
// tconv2 prepped bf16 split weights: [3 kc][192 n][64 k]
__device__ __align__(16) __nv_bfloat16 g_bh[3*192*64];
__device__ __align__(16) __nv_bfloat16 g_bl[3*192*64];
// tconv1 prepped bf16 split weights: [192 n][96 k]  (k = tap*32 + ci)
__device__ __align__(16) __nv_bfloat16 g_b1h[192*96];
__device__ __align__(16) __nv_bfloat16 g_b1l[192*96];

// ---------------- graph preprocessing ---------------------------------------
__global__ void k_zero() {
    int i = blockIdx.x * blockDim.x + threadIdx.x;
    if (i < NN) { g_deg[i] = 0.f; g_rowcount[i] = 0; g_cursor[i] = 0; }
}

__global__ void k_deg(const int* __restrict__ ei, const float* __restrict__ ew) {
    int e = blockIdx.x * blockDim.x + threadIdx.x;
    if (e < EE) {
        int r = ei[e], c = ei[EE + e];
        float w = (r == c) ? 0.f : ew[e];
        atomicAdd(&g_deg[r], w);
        atomicAdd(&g_rowcount[r], 1);
    }
}

__global__ void k_scandis() {
    int tid = threadIdx.x;
    for (int i = tid; i < NN; i += 1024) {
        float d = g_deg[i];
        g_dis[i] = (d > 0.f) ? rsqrtf(d) : 0.f;
    }
    int v0 = g_rowcount[2 * tid], v1 = g_rowcount[2 * tid + 1];
    int s  = v0 + v1;
    int lane = tid & 31, wid = tid >> 5;
    int sc = s;
#pragma unroll
    for (int o = 1; o < 32; o <<= 1) {
        int t = __shfl_up_sync(0xffffffffu, sc, o);
        if (lane >= o) sc += t;
    }
    __shared__ int ws[32];
    if (lane == 31) ws[wid] = sc;
    __syncthreads();
    if (wid == 0) {
        int w = ws[lane];
#pragma unroll
        for (int o = 1; o < 32; o <<= 1) {
            int t = __shfl_up_sync(0xffffffffu, w, o);
            if (lane >= o) w += t;
        }
        ws[lane] = w;
    }
    __syncthreads();
    int base = ((wid > 0) ? ws[wid - 1] : 0) + sc - s;
    g_rowstart[2 * tid + 1] = base + v0;
    g_rowstart[2 * tid + 2] = base + v0 + v1;
    if (tid == 0) g_rowstart[0] = 0;
}

__global__ void k_scatter(const int* __restrict__ ei, const float* __restrict__ ew) {
    int e = blockIdx.x * blockDim.x + threadIdx.x;
    if (e < EE) {
        int r = ei[e], c = ei[EE + e];
        float w = (r == c) ? 0.f : ew[e];
        int pos = g_rowstart[r] + atomicAdd(&g_cursor[r], 1);
        g_ccol[pos]  = c;
        g_cnorm[pos] = -g_dis[r] * w * g_dis[c];
    }
}

// ---------------- weight prep: fp32 -> bf16 hi/lo ----------------------------
__global__ void k_wprep(const float* __restrict__ w1, const float* __restrict__ w2,
                        const float* __restrict__ w3,
                        const float* __restrict__ v1, const float* __restrict__ v2,
                        const float* __restrict__ v3) {
    int idx = blockIdx.x * blockDim.x + threadIdx.x;
    // tconv2: [kc][n][64]
    if (idx < 3 * 192 * 64) {
        int kc = idx / (192 * 64);
        int n  = (idx / 64) % 192;
        int ci = idx % 64;
        int j  = n / 64, co = n % 64;
        const float* wj = (j == 0) ? w1 : ((j == 1) ? w2 : w3);
        float v = wj[(co * 64 + ci) * 3 + kc];
        __nv_bfloat16 h = __float2bfloat16(v);
        g_bh[idx] = h;
        g_bl[idx] = __float2bfloat16(v - __bfloat162float(h));
    }
    // tconv1: [n][96], k = tap*32 + ci
    int idx1 = idx - 3 * 192 * 64;
    if (idx1 >= 0 && idx1 < 192 * 96) {
        int n  = idx1 / 96;
        int k  = idx1 % 96;
        int tap = k >> 5, ci = k & 31;
        int j  = n / 64, co = n % 64;
        const float* wj = (j == 0) ? v1 : ((j == 1) ? v2 : v3);
        float v = wj[(co * 32 + ci) * 3 + tap];
        __nv_bfloat16 h = __float2bfloat16(v);
        g_b1h[idx1] = h;
        g_b1l[idx1] = __float2bfloat16(v - __bfloat162float(h));
    }
}

// ---------------- tconv1 via HMMA --------------------------------------------
// GEMM: M=57344 (nb,t), N=192 (3 gates x 64 co), K=96 (3 taps x 32 ci).
// Single K stage. A, B, D all in smem; D overlays A+B after MMAs.
#define AP1 104   /* bf16 pitch, conflict-free frags */
#define BP1 104
#define DP1 196   /* float pitch */
#define O1_AH   768
#define O1_AL   (O1_AH + 128*AP1*2)        /* +26624 */
#define O1_BH   (O1_AL + 128*AP1*2)        /* 54016 */
#define O1_BL   (O1_BH + 192*BP1*2)        /* +39936 */
#define SMEM_H1 (O1_BL + 192*BP1*2)        /* 133888; D (100352) overlays @O1_AH */

__global__ void __launch_bounds__(256, 1) k_tconv1_hmma(
    const float* __restrict__ x,
    const float* __restrict__ bb1, const float* __restrict__ bb2,
    const float* __restrict__ bb3)
{
    extern __shared__ char smem[];
    float*         sbias = (float*)smem;
    __nv_bfloat16* sAh   = (__nv_bfloat16*)(smem + O1_AH);
    __nv_bfloat16* sAl   = (__nv_bfloat16*)(smem + O1_AL);
    __nv_bfloat16* sBh   = (__nv_bfloat16*)(smem + O1_BH);
    __nv_bfloat16* sBl   = (__nv_bfloat16*)(smem + O1_BL);
    float*         sD    = (float*)(smem + O1_AH);   /* overlay */

    int tid = threadIdx.x;
    if (tid < 64) {
        sbias[tid]       = bb1[tid];
        sbias[64 + tid]  = bb2[tid];
        sbias[128 + tid] = bb3[tid];
    }

    int rA = tid >> 1, half = tid & 1;
    long R = (long)blockIdx.x * 128 + rA;
    int nb = (int)(R / 14), t = (int)(R % 14);
    int b = nb & 1, n = nb >> 1;

    // ---- stage A: 48 floats per thread -> bf16 hi/lo, pitch AP1
    {
        const float* xb = x + (long)b * (TT * NN * CI1) + (long)n * CI1;
#pragma unroll
        for (int k4 = 0; k4 < 12; k4++) {
            int k = half * 48 + k4 * 4;
            int tap = k >> 5, ci = k & 31;
            float4 v = __ldg((const float4*)(xb + (long)(t + tap) * (NN * CI1) + ci));
            float hx = __bfloat162float(__float2bfloat16(v.x));
            float hy = __bfloat162float(__float2bfloat16(v.y));
            float hz = __bfloat162float(__float2bfloat16(v.z));
            float hw = __bfloat162float(__float2bfloat16(v.w));
            uint32_t off = (uint32_t)rA * (AP1 * 2) + half * 96 + k4 * 8;
            *(uint2*)((char*)sAh + off) = make_uint2(pkbf2(hx, hy), pkbf2(hz, hw));
            *(uint2*)((char*)sAl + off) = make_uint2(pkbf2(v.x - hx, v.y - hy),
                                                     pkbf2(v.z - hz, v.w - hw));
        }
    }
    // ---- stage B: 192 x 96 bf16 hi/lo, pitch BP1
    for (int u = tid; u < 192 * 12; u += 256) {
        int nn2 = u / 12, c16 = u % 12;
        uint32_t dst = (uint32_t)nn2 * (BP1 * 2) + c16 * 16;
        *(uint4*)((char*)sBh + dst) = *(const uint4*)((const char*)g_b1h + nn2 * 192 + c16 * 16);
        *(uint4*)((char*)sBl + dst) = *(const uint4*)((const char*)g_b1l + nn2 * 192 + c16 * 16);
    }
    __syncthreads();

    int lane = tid & 31, w = tid >> 5;
    int m0 = (w & 3) * 32;
    int n0 = (w >> 2) * 96;
    int g  = lane >> 2, tg = lane & 3;

    float acc[2][12][4];
#pragma unroll
    for (int s = 0; s < 2; s++)
#pragma unroll
        for (int nt = 0; nt < 12; nt++)
#pragma unroll
            for (int q = 0; q < 4; q++) acc[s][nt][q] = 0.f;

#pragma unroll
    for (int ks = 0; ks < 6; ks++) {
        uint32_t ah[2][4], al[2][4];
#pragma unroll
        for (int s = 0; s < 2; s++) {
            int row = m0 + s * 16 + g;
            const __nv_bfloat16* ph = sAh + row * AP1 + ks * 16 + 2 * tg;
            const __nv_bfloat16* pl = sAl + row * AP1 + ks * 16 + 2 * tg;
            ah[s][0] = *(const uint32_t*)(ph);
            ah[s][1] = *(const uint32_t*)(ph + 8 * AP1);
            ah[s][2] = *(const uint32_t*)(ph + 8);
            ah[s][3] = *(const uint32_t*)(ph + 8 * AP1 + 8);
            al[s][0] = *(const uint32_t*)(pl);
            al[s][1] = *(const uint32_t*)(pl + 8 * AP1);
            al[s][2] = *(const uint32_t*)(pl + 8);
            al[s][3] = *(const uint32_t*)(pl + 8 * AP1 + 8);
        }
#pragma unroll
        for (int nt = 0; nt < 12; nt++) {
            int nn2 = n0 + nt * 8 + g;
            const uint32_t* pbh = (const uint32_t*)(sBh + nn2 * BP1 + ks * 16 + 2 * tg);
            const uint32_t* pbl = (const uint32_t*)(sBl + nn2 * BP1 + ks * 16 + 2 * tg);
            uint32_t b0h = pbh[0], b1h = pbh[4];
            uint32_t b0l = pbl[0], b1l = pbl[4];
#pragma unroll
            for (int s = 0; s < 2; s++) {
                mma_bf16(acc[s][nt], ah[s], b0h, b1h);
                mma_bf16(acc[s][nt], ah[s], b0l, b1l);
                mma_bf16(acc[s][nt], al[s], b0h, b1h);
            }
        }
    }
    __syncthreads();   // A/B dead; D overlays
#pragma unroll
    for (int s = 0; s < 2; s++)
#pragma unroll
        for (int nt = 0; nt < 12; nt++) {
            int row = m0 + s * 16 + g;
            int col = n0 + nt * 8 + 2 * tg;
            *(float2*)(sD + (long)row * DP1 + col) =
                make_float2(acc[s][nt][0], acc[s][nt][1]);
            *(float2*)(sD + (long)(row + 8) * DP1 + col) =
                make_float2(acc[s][nt][2], acc[s][nt][3]);
        }
    __syncthreads();
    {
        float* orow = g_t1 + ((long)nb * T1 + t) * 64;
        const float* drow = sD + (long)rA * DP1;
#pragma unroll
        for (int i = 0; i < 32; i++) {
            int co = half * 32 + i;
            float a1 = drow[co]       + sbias[co];
            float a2 = drow[64 + co]  + sbias[64 + co];
            float a3 = drow[128 + co] + sbias[128 + co];
            float sg = __fdividef(1.f, 1.f + __expf(-a2));
            float v  = a1 + sg + a3;
            orow[co] = (v > 0.f) ? v : 0.f;
        }
    }
}

// ---------------- tconv2 via HMMA (B in smem per kc, D overlays A+B) ---------
#define AP2 72
#define BP2 72
#define DP2 196
#define O2_AH   768
#define O2_AL   (O2_AH + 128*AP2*2)        /* +18432 */
#define O2_BH   (O2_AL + 128*AP2*2)        /* 37632 */
#define O2_BL   (O2_BH + 192*BP2*2)        /* +27648 */
#define O2_END  (O2_BL + 192*BP2*2)        /* 92928 */
#define SMEM_H2 (O2_AH + 128*DP2*4)        /* 768 + 100352 = 101120 */

__global__ void __launch_bounds__(256, 1) k_tconv2_hmma(
    const float* __restrict__ bb1, const float* __restrict__ bb2,
    const float* __restrict__ bb3)
{
    extern __shared__ char smem[];
    float*         sbias = (float*)smem;
    __nv_bfloat16* sAh   = (__nv_bfloat16*)(smem + O2_AH);
    __nv_bfloat16* sAl   = (__nv_bfloat16*)(smem + O2_AL);
    __nv_bfloat16* sBh   = (__nv_bfloat16*)(smem + O2_BH);
    __nv_bfloat16* sBl   = (__nv_bfloat16*)(smem + O2_BL);
    float*         sD    = (float*)(smem + O2_AH);

    int tid = threadIdx.x;
    if (tid < 64) {
        sbias[tid]       = bb1[tid];
        sbias[64 + tid]  = bb2[tid];
        sbias[128 + tid] = bb3[tid];
    }

    int lane = tid & 31, w = tid >> 5;
    int m0 = (w & 3) * 32;
    int n0 = (w >> 2) * 96;
    int g  = lane >> 2, tg = lane & 3;

    float acc[2][12][4];
#pragma unroll
    for (int s = 0; s < 2; s++)
#pragma unroll
        for (int nt = 0; nt < 12; nt++)
#pragma unroll
            for (int q = 0; q < 4; q++) acc[s][nt][q] = 0.f;

    int rA = tid >> 1, half = tid & 1;
    long R = (long)blockIdx.x * 128 + rA;
    int nb = (int)(R / 12), t = (int)(R % 12);

    for (int kc = 0; kc < 3; kc++) {
        __syncthreads();
        // ---- stage A (rows of g_t2 at t+kc)
        {
            const float4* src = (const float4*)(g_t2 + ((long)nb * T1 + t + kc) * 64)
                                + half * 8;
            uint32_t off = (uint32_t)rA * (AP2 * 2) + half * 64;
            uint2* dh = (uint2*)((char*)sAh + off);
            uint2* dl = (uint2*)((char*)sAl + off);
#pragma unroll
            for (int v4 = 0; v4 < 8; v4++) {
                float4 xv = __ldg(&src[v4]);
                float hx = __bfloat162float(__float2bfloat16(xv.x));
                float hy = __bfloat162float(__float2bfloat16(xv.y));
                float hz = __bfloat162float(__float2bfloat16(xv.z));
                float hw = __bfloat162float(__float2bfloat16(xv.w));
                dh[v4] = make_uint2(pkbf2(hx, hy), pkbf2(hz, hw));
                dl[v4] = make_uint2(pkbf2(xv.x - hx, xv.y - hy),
                                    pkbf2(xv.z - hz, xv.w - hw));
            }
        }
        // ---- stage B for this kc
        {
            const char* bh = (const char*)(g_bh + (long)kc * 192 * 64);
            const char* bl = (const char*)(g_bl + (long)kc * 192 * 64);
            for (int u = tid; u < 192 * 8; u += 256) {
                int nn2 = u >> 3, c16 = u & 7;
                uint32_t dst = (uint32_t)nn2 * (BP2 * 2) + c16 * 16;
                *(uint4*)((char*)sBh + dst) = *(const uint4*)(bh + nn2 * 128 + c16 * 16);
                *(uint4*)((char*)sBl + dst) = *(const uint4*)(bl + nn2 * 128 + c16 * 16);
            }
        }
        __syncthreads();

#pragma unroll
        for (int ks = 0; ks < 4; ks++) {
            uint32_t ah[2][4], al[2][4];
#pragma unroll
            for (int s = 0; s < 2; s++) {
                int row = m0 + s * 16 + g;
                const __nv_bfloat16* ph = sAh + row * AP2 + ks * 16 + 2 * tg;
                const __nv_bfloat16* pl = sAl + row * AP2 + ks * 16 + 2 * tg;
                ah[s][0] = *(const uint32_t*)(ph);
                ah[s][1] = *(const uint32_t*)(ph + 8 * AP2);
                ah[s][2] = *(const uint32_t*)(ph + 8);
                ah[s][3] = *(const uint32_t*)(ph + 8 * AP2 + 8);
                al[s][0] = *(const uint32_t*)(pl);
                al[s][1] = *(const uint32_t*)(pl + 8 * AP2);
                al[s][2] = *(const uint32_t*)(pl + 8);
                al[s][3] = *(const uint32_t*)(pl + 8 * AP2 + 8);
            }
#pragma unroll
            for (int nt = 0; nt < 12; nt++) {
                int nn2 = n0 + nt * 8 + g;
                const uint32_t* pbh = (const uint32_t*)(sBh + nn2 * BP2 + ks * 16 + 2 * tg);
                const uint32_t* pbl = (const uint32_t*)(sBl + nn2 * BP2 + ks * 16 + 2 * tg);
                uint32_t b0h = pbh[0], b1h = pbh[4];
                uint32_t b0l = pbl[0], b1l = pbl[4];
#pragma unroll
                for (int s = 0; s < 2; s++) {
                    mma_bf16(acc[s][nt], ah[s], b0h, b1h);
                    mma_bf16(acc[s][nt], ah[s], b0l, b1l);
                    mma_bf16(acc[s][nt], al[s], b0h, b1h);
                }
            }
        }
    }
    __syncthreads();
#pragma unroll
    for (int s = 0; s < 2; s++)
#pragma unroll
        for (int nt = 0; nt < 12; nt++) {
            int row = m0 + s * 16 + g;
            int col = n0 + nt * 8 + 2 * tg;
            *(float2*)(sD + (long)row * DP2 + col) =
                make_float2(acc[s][nt][0], acc[s][nt][1]);
            *(float2*)(sD + (long)(row + 8) * DP2 + col) =
                make_float2(acc[s][nt][2], acc[s][nt][3]);
        }
    __syncthreads();
    {
        float* orow = g_t3 + ((long)nb * T2 + t) * 64;
        const float* drow = sD + (long)rA * DP2;
#pragma unroll
        for (int i = 0; i < 32; i++) {
            int co = half * 32 + i;
            float a1 = drow[co]       + sbias[co];
            float a2 = drow[64 + co]  + sbias[64 + co];
            float a3 = drow[128 + co] + sbias[128 + co];
            float sg = __fdividef(1.f, 1.f + __expf(-a2));
            float v  = a1 + sg + a3;
            orow[co] = (v > 0.f) ? v : 0.f;
        }
    }
}

// ---------------- ChebConv propagation (CSR gather) --------------------------
__global__ void k_prop(const float4* __restrict__ z, float4* __restrict__ out,
                       const float4* __restrict__ x0, int mode)
{
    int n = blockIdx.x;
    int tid = threadIdx.x;
    int e0 = g_rowstart[n], e1 = g_rowstart[n + 1];
    float4 acc = make_float4(0.f, 0.f, 0.f, 0.f);
    for (int e = e0; e < e1; e++) {
        int   c  = __ldg(&g_ccol[e]);
        float nm = __ldg(&g_cnorm[e]);
        float4 v = __ldg(&z[(long)c * F14 + tid]);
        acc.x += nm * v.x; acc.y += nm * v.y;
        acc.z += nm * v.z; acc.w += nm * v.w;
    }
    if (mode) {
        float4 v0 = __ldg(&x0[(long)n * F14 + tid]);
        acc.x = 2.f * acc.x - v0.x; acc.y = 2.f * acc.y - v0.y;
        acc.z = 2.f * acc.z - v0.z; acc.w = 2.f * acc.w - v0.w;
    }
    out[(long)n * F14 + tid] = acc;
}

// ---------------- fused Cheb GEMM (proven scalar version) --------------------
__global__ void __launch_bounds__(448) k_cheb(const float* __restrict__ W,
                                              const float* __restrict__ bias)
{
    extern __shared__ char smraw[];
    u64* sW = (u64*)smraw;
    for (int idx = threadIdx.x; idx < 3 * 64 * 32; idx += 448) {
        int p = idx & 31;
        int jc = idx >> 5;
        sW[idx] = pk2(W[jc * 64 + 2 * p], W[jc * 64 + 2 * p + 1]);
    }
    __syncthreads();

    int p  = threadIdx.x & 31;
    int g  = threadIdx.x >> 5;
    int nb = blockIdx.x * 14 + g;
    if (nb >= NB_TOTAL) return;

    const float4* x0 = (const float4*)(g_t1  + (long)nb * T1 * 64);
    const float4* x1 = (const float4*)(g_tx1 + (long)nb * T1 * 64);
    const float4* x2 = (const float4*)(g_tx2 + (long)nb * T1 * 64);

    u64 acc[T1];
#pragma unroll
    for (int t = 0; t < T1; t++) acc[t] = 0ull;

#pragma unroll
    for (int c4 = 0; c4 < 16; c4++) {
        u64 w0[4], w1[4], w2[4];
#pragma unroll
        for (int u = 0; u < 4; u++) {
            int c = c4 * 4 + u;
            w0[u] = sW[(0 * 64 + c) * 32 + p];
            w1[u] = sW[(1 * 64 + c) * 32 + p];
            w2[u] = sW[(2 * 64 + c) * 32 + p];
        }
#pragma unroll
        for (int t = 0; t < T1; t++) {
            float4 v0 = __ldg(&x0[t * 16 + c4]);
            float4 v1 = __ldg(&x1[t * 16 + c4]);
            float4 v2 = __ldg(&x2[t * 16 + c4]);
            u64 a = acc[t];
            a = fma2(pk2(v0.x, v0.x), w0[0], a);
            a = fma2(pk2(v0.y, v0.y), w0[1], a);
            a = fma2(pk2(v0.z, v0.z), w0[2], a);
            a = fma2(pk2(v0.w, v0.w), w0[3], a);
            a = fma2(pk2(v1.x, v1.x), w1[0], a);
            a = fma2(pk2(v1.y, v1.y), w1[1], a);
            a = fma2(pk2(v1.z, v1.z), w1[2], a);
            a = fma2(pk2(v1.w, v1.w), w1[3], a);
            a = fma2(pk2(v2.x, v2.x), w2[0], a);
            a = fma2(pk2(v2.y, v2.y), w2[1], a);
            a = fma2(pk2(v2.z, v2.z), w2[2], a);
            a = fma2(pk2(v2.w, v2.w), w2[3], a);
            acc[t] = a;
        }
    }

    float2 bv = __ldg((const float2*)bias + p);
    float* ob = g_t2 + (long)nb * T1 * 64 + 2 * p;
#pragma unroll
    for (int t = 0; t < T1; t++) {
        float2 a = upk2(acc[t]);
        float vx = a.x + bv.x, vy = a.y + bv.y;
        vx = (vx > 0.f) ? vx : 0.f;
        vy = (vy > 0.f) ? vy : 0.f;
        *(float2*)(ob + t * 64) = make_float2(vx, vy);
    }
}

// ---------------- BN (channel axis = node) + final transpose -----------------
__global__ void k_bn(const float* __restrict__ gamma, const float* __restrict__ beta,
                     float* __restrict__ out)
{
    int n = blockIdx.x;
    const float* tp = g_t3 + (long)n * (BB * T2 * 64);
    float s = 0.f, s2 = 0.f;
    for (int i = threadIdx.x; i < BB * T2 * 64; i += 256) {
        float v = tp[i]; s += v; s2 += v * v;
    }
    __shared__ float rs[8], rs2[8];
    for (int o = 16; o; o >>= 1) {
        s  += __shfl_down_sync(0xffffffff, s,  o);
        s2 += __shfl_down_sync(0xffffffff, s2, o);
    }
    int lane = threadIdx.x & 31, wid = threadIdx.x >> 5;
    if (lane == 0) { rs[wid] = s; rs2[wid] = s2; }
    __syncthreads();
    __shared__ float smu, srstd;
    if (wid == 0) {
        float a  = (lane < 8) ? rs[lane]  : 0.f;
        float a2 = (lane < 8) ? rs2[lane] : 0.f;
        for (int o = 4; o; o >>= 1) {
            a  += __shfl_down_sync(0xffffffff, a,  o);
            a2 += __shfl_down_sync(0xffffffff, a2, o);
        }
        if (lane == 0) {
            float mu  = a / 1536.f;
            float var = a2 / 1536.f - mu * mu;
            smu = mu; srstd = rsqrtf(var + 1e-5f);
        }
    }
    __syncthreads();
    float mu = smu, rstd = srstd;
    float ga = gamma[n], be = beta[n];
    for (int i = threadIdx.x; i < BB * T2 * 64; i += 256) {
        float v = (tp[i] - mu) * rstd * ga + be;
        int c = i & 63;
        int t = (i >> 6) % T2;
        int b = i / (T2 * 64);
        out[(((long)b * T2 + t) * NN + n) * 64 + c] = v;
    }
}

// ---------------- launch -----------------------------------------------------
extern "C" void kernel_launch(void* const* d_in, const int* in_sizes, int n_in,
                              void* d_out, int out_size)
{
    const float* X    = (const float*)d_in[0];
    const int*   ei   = (const int*)  d_in[1];
    const float* ew   = (const float*)d_in[2];
    const float* t1w1 = (const float*)d_in[3];
    const float* t1b1 = (const float*)d_in[4];
    const float* t1w2 = (const float*)d_in[5];
    const float* t1b2 = (const float*)d_in[6];
    const float* t1w3 = (const float*)d_in[7];
    const float* t1b3 = (const float*)d_in[8];
    const float* chw  = (const float*)d_in[9];
    const float* chb  = (const float*)d_in[10];
    const float* t2w1 = (const float*)d_in[11];
    const float* t2b1 = (const float*)d_in[12];
    const float* t2w2 = (const float*)d_in[13];
    const float* t2b2 = (const float*)d_in[14];
    const float* t2w3 = (const float*)d_in[15];
    const float* t2b3 = (const float*)d_in[16];
    const float* gam  = (const float*)d_in[17];
    const float* bet  = (const float*)d_in[18];
    float* out = (float*)d_out;

    void *p_t1, *p_tx1, *p_tx2;
    cudaGetSymbolAddress(&p_t1,  g_t1);
    cudaGetSymbolAddress(&p_tx1, g_tx1);
    cudaGetSymbolAddress(&p_tx2, g_tx2);

    const int smemC = 3 * 64 * 32 * 8;   // 49152
    cudaFuncSetAttribute(k_cheb,         cudaFuncAttributeMaxDynamicSharedMemorySize, smemC);
    cudaFuncSetAttribute(k_tconv1_hmma,  cudaFuncAttributeMaxDynamicSharedMemorySize, SMEM_H1);
    cudaFuncSetAttribute(k_tconv2_hmma,  cudaFuncAttributeMaxDynamicSharedMemorySize, SMEM_H2);

    const int gridC = (NB_TOTAL + 13) / 14;  // 293

    k_zero   <<<(NN + 255) / 256, 256>>>();                         // 0
    k_deg    <<<EE / 256, 256>>>(ei, ew);                           // 1
    k_wprep  <<<((3*192*64 + 192*96) + 255) / 256, 256>>>(          // 2
        t2w1, t2w2, t2w3, t1w1, t1w2, t1w3);

    // 3 (profiled slot): tconv1 HMMA, 448 tiles of 128 (nb,t) rows
    k_tconv1_hmma<<<NB_TOTAL * T1 / 128, 256, SMEM_H1>>>(X, t1b1, t1b2, t1b3);

    k_scandis<<<1, 1024>>>();                                       // 4
    k_scatter<<<EE / 256, 256>>>(ei, ew);                           // 5

    k_prop<<<NN, F14>>>((const float4*)p_t1,  (float4*)p_tx1, (const float4*)p_t1, 0);
    k_prop<<<NN, F14>>>((const float4*)p_tx1, (float4*)p_tx2, (const float4*)p_t1, 1);

    k_cheb<<<gridC, 448, smemC>>>(chw, chb);

    // tconv2 HMMA: 384 tiles
    k_tconv2_hmma<<<NB_TOTAL * T2 / 128, 256, SMEM_H2>>>(t2b1, t2b2, t2b3);

    k_bn<<<NN, 256>>>(gam, bet, out);
}

// round 10
// speedup vs baseline: 2.4383x; 1.2787x over previous
#include <cuda_runtime.h>
#include <cuda_bf16.h>
#include <math.h>
#include <stdint.h>

#define BB   2
#define TT   16
#define NN   2048
#define CI1  32
#define CHH  64
#define EE   32768
#define T1   14
#define T2   12
#define F1   (BB*T1*CHH)
#define F14  (F1/4)
#define NB_TOTAL (NN*BB)

typedef unsigned long long u64;

__device__ __forceinline__ uint32_t pkbf2(float a, float b) {
    __nv_bfloat162 h = __floats2bfloat162_rn(a, b);
    return *reinterpret_cast<uint32_t*>(&h);
}
__device__ __forceinline__ void mma_bf16(float* d, const uint32_t* a,
                                         uint32_t b0, uint32_t b1) {
    asm volatile(
        "mma.sync.aligned.m16n8k16.row.col.f32.bf16.bf16.f32 "
        "{%0,%1,%2,%3}, {%4,%5,%6,%7}, {%8,%9}, {%0,%1,%2,%3};"
        : "+f"(d[0]), "+f"(d[1]), "+f"(d[2]), "+f"(d[3])
        : "r"(a[0]), "r"(a[1]), "r"(a[2]), "r"(a[3]), "r"(b0), "r"(b1));
}

// ---------------- scratch ----------------------------------------------------
__device__ __align__(16) float g_t1 [NB_TOTAL*T1*CHH];
__device__ __align__(16) float g_tx1[NB_TOTAL*T1*CHH];
__device__ __align__(16) float g_tx2[NB_TOTAL*T1*CHH];
__device__ __align__(16) float g_t2 [NB_TOTAL*T1*CHH];
__device__ __align__(16) float g_t3 [NB_TOTAL*T2*CHH];
__device__ float g_deg[NN];
__device__ float g_dis[NN];
__device__ int   g_rowcount[NN];
__device__ int   g_rowstart[NN+1];
__device__ int   g_cursor[NN];
__device__ int   g_ccol[EE];
__device__ float g_cnorm[EE];
// tconv2 prepped weights: [3 kc][192 n][64 k]
__device__ __align__(16) __nv_bfloat16 g_bh[3*192*64];
__device__ __align__(16) __nv_bfloat16 g_bl[3*192*64];
// tconv1 prepped weights: [192 n][96 k]
__device__ __align__(16) __nv_bfloat16 g_b1h[192*96];
__device__ __align__(16) __nv_bfloat16 g_b1l[192*96];
// cheb prepped weights: [3 j][64 n][64 k]  (n=co, k=ci)
__device__ __align__(16) __nv_bfloat16 g_chh[3*64*64];
__device__ __align__(16) __nv_bfloat16 g_chl[3*64*64];

// ---------------- graph preprocessing ---------------------------------------
__global__ void k_zero() {
    int i = blockIdx.x * blockDim.x + threadIdx.x;
    if (i < NN) { g_deg[i] = 0.f; g_rowcount[i] = 0; g_cursor[i] = 0; }
}

__global__ void k_deg(const int* __restrict__ ei, const float* __restrict__ ew) {
    int e = blockIdx.x * blockDim.x + threadIdx.x;
    if (e < EE) {
        int r = ei[e], c = ei[EE + e];
        float w = (r == c) ? 0.f : ew[e];
        atomicAdd(&g_deg[r], w);
        atomicAdd(&g_rowcount[r], 1);
    }
}

__global__ void k_scandis() {
    int tid = threadIdx.x;
    for (int i = tid; i < NN; i += 1024) {
        float d = g_deg[i];
        g_dis[i] = (d > 0.f) ? rsqrtf(d) : 0.f;
    }
    int v0 = g_rowcount[2 * tid], v1 = g_rowcount[2 * tid + 1];
    int s  = v0 + v1;
    int lane = tid & 31, wid = tid >> 5;
    int sc = s;
#pragma unroll
    for (int o = 1; o < 32; o <<= 1) {
        int t = __shfl_up_sync(0xffffffffu, sc, o);
        if (lane >= o) sc += t;
    }
    __shared__ int ws[32];
    if (lane == 31) ws[wid] = sc;
    __syncthreads();
    if (wid == 0) {
        int w = ws[lane];
#pragma unroll
        for (int o = 1; o < 32; o <<= 1) {
            int t = __shfl_up_sync(0xffffffffu, w, o);
            if (lane >= o) w += t;
        }
        ws[lane] = w;
    }
    __syncthreads();
    int base = ((wid > 0) ? ws[wid - 1] : 0) + sc - s;
    g_rowstart[2 * tid + 1] = base + v0;
    g_rowstart[2 * tid + 2] = base + v0 + v1;
    if (tid == 0) g_rowstart[0] = 0;
}

__global__ void k_scatter(const int* __restrict__ ei, const float* __restrict__ ew) {
    int e = blockIdx.x * blockDim.x + threadIdx.x;
    if (e < EE) {
        int r = ei[e], c = ei[EE + e];
        float w = (r == c) ? 0.f : ew[e];
        int pos = g_rowstart[r] + atomicAdd(&g_cursor[r], 1);
        g_ccol[pos]  = c;
        g_cnorm[pos] = -g_dis[r] * w * g_dis[c];
    }
}

// ---------------- weight prep: fp32 -> bf16 hi/lo ----------------------------
__global__ void k_wprep(const float* __restrict__ w1, const float* __restrict__ w2,
                        const float* __restrict__ w3,
                        const float* __restrict__ v1, const float* __restrict__ v2,
                        const float* __restrict__ v3,
                        const float* __restrict__ cw) {
    int idx = blockIdx.x * blockDim.x + threadIdx.x;
    if (idx < 3 * 192 * 64) {                       // tconv2
        int kc = idx / (192 * 64);
        int n  = (idx / 64) % 192;
        int ci = idx % 64;
        int j  = n / 64, co = n % 64;
        const float* wj = (j == 0) ? w1 : ((j == 1) ? w2 : w3);
        float v = wj[(co * 64 + ci) * 3 + kc];
        __nv_bfloat16 h = __float2bfloat16(v);
        g_bh[idx] = h;
        g_bl[idx] = __float2bfloat16(v - __bfloat162float(h));
    }
    int idx1 = idx - 3 * 192 * 64;                  // tconv1
    if (idx1 >= 0 && idx1 < 192 * 96) {
        int n  = idx1 / 96;
        int k  = idx1 % 96;
        int tap = k >> 5, ci = k & 31;
        int j  = n / 64, co = n % 64;
        const float* wj = (j == 0) ? v1 : ((j == 1) ? v2 : v3);
        float v = wj[(co * 32 + ci) * 3 + tap];
        __nv_bfloat16 h = __float2bfloat16(v);
        g_b1h[idx1] = h;
        g_b1l[idx1] = __float2bfloat16(v - __bfloat162float(h));
    }
    int idx2 = idx1 - 192 * 96;                     // cheb
    if (idx2 >= 0 && idx2 < 3 * 64 * 64) {
        int j  = idx2 / (64 * 64);
        int n  = (idx2 / 64) % 64;   // co
        int k  = idx2 % 64;          // ci
        float v = cw[(j * 64 + k) * 64 + n];
        __nv_bfloat16 h = __float2bfloat16(v);
        g_chh[idx2] = h;
        g_chl[idx2] = __float2bfloat16(v - __bfloat162float(h));
    }
}

// =============================================================================
// tconv1 HMMA: M=57344 (nb,t14), N=192, K=96. 512 thr = 16 warps (M16 x N96).
// In-register gating epilogue (warp owns all 3 gates for its 32 co cols).
// =============================================================================
#define AP1 104
#define BP1 104
#define O1_AH   768
#define O1_AL   (O1_AH + 128*AP1*2)
#define O1_BH   (O1_AL + 128*AP1*2)
#define O1_BL   (O1_BH + 192*BP1*2)
#define SMEM_H1 (O1_BL + 192*BP1*2)   /* 133888 */

__global__ void __launch_bounds__(512, 1) k_tconv1_hmma(
    const float* __restrict__ x,
    const float* __restrict__ bb1, const float* __restrict__ bb2,
    const float* __restrict__ bb3)
{
    extern __shared__ char smem[];
    float*         sbias = (float*)smem;
    __nv_bfloat16* sAh   = (__nv_bfloat16*)(smem + O1_AH);
    __nv_bfloat16* sAl   = (__nv_bfloat16*)(smem + O1_AL);
    __nv_bfloat16* sBh   = (__nv_bfloat16*)(smem + O1_BH);
    __nv_bfloat16* sBl   = (__nv_bfloat16*)(smem + O1_BL);

    int tid = threadIdx.x;
    if (tid < 64) {
        sbias[tid]       = bb1[tid];
        sbias[64 + tid]  = bb2[tid];
        sbias[128 + tid] = bb3[tid];
    }

    // ---- stage A: 128 rows x 96 k; 4 threads/row, 24 k each
    {
        int rA = tid >> 2, quarter = tid & 3;
        long R = (long)blockIdx.x * 128 + rA;
        int nb = (int)(R / 14), t = (int)(R % 14);
        int b = nb & 1, n = nb >> 1;
        const float* xb = x + (long)b * (TT * NN * CI1) + (long)n * CI1;
#pragma unroll
        for (int k4 = 0; k4 < 6; k4++) {
            int k = quarter * 24 + k4 * 4;
            int tap = k >> 5, ci = k & 31;
            float4 v = __ldg((const float4*)(xb + (long)(t + tap) * (NN * CI1) + ci));
            float hx = __bfloat162float(__float2bfloat16(v.x));
            float hy = __bfloat162float(__float2bfloat16(v.y));
            float hz = __bfloat162float(__float2bfloat16(v.z));
            float hw = __bfloat162float(__float2bfloat16(v.w));
            uint32_t off = (uint32_t)rA * (AP1 * 2) + k * 2;
            *(uint2*)((char*)sAh + off) = make_uint2(pkbf2(hx, hy), pkbf2(hz, hw));
            *(uint2*)((char*)sAl + off) = make_uint2(pkbf2(v.x - hx, v.y - hy),
                                                     pkbf2(v.z - hz, v.w - hw));
        }
    }
    // ---- stage B: 192 x 96 bf16 hi/lo
    for (int u = tid; u < 192 * 12; u += 512) {
        int nn2 = u / 12, c16 = u % 12;
        uint32_t dst = (uint32_t)nn2 * (BP1 * 2) + c16 * 16;
        *(uint4*)((char*)sBh + dst) = *(const uint4*)((const char*)g_b1h + nn2 * 192 + c16 * 16);
        *(uint4*)((char*)sBl + dst) = *(const uint4*)((const char*)g_b1l + nn2 * 192 + c16 * 16);
    }
    __syncthreads();

    int lane = tid & 31, w = tid >> 5;
    int m0 = (w >> 1) * 16;
    int c0 = (w & 1) * 32;
    int g  = lane >> 2, tg = lane & 3;

    float acc[12][4];
#pragma unroll
    for (int nt = 0; nt < 12; nt++)
#pragma unroll
        for (int q = 0; q < 4; q++) acc[nt][q] = 0.f;

#pragma unroll
    for (int ks = 0; ks < 6; ks++) {
        uint32_t ah[4], al[4];
        {
            int row = m0 + g;
            const __nv_bfloat16* ph = sAh + row * AP1 + ks * 16 + 2 * tg;
            const __nv_bfloat16* pl = sAl + row * AP1 + ks * 16 + 2 * tg;
            ah[0] = *(const uint32_t*)(ph);
            ah[1] = *(const uint32_t*)(ph + 8 * AP1);
            ah[2] = *(const uint32_t*)(ph + 8);
            ah[3] = *(const uint32_t*)(ph + 8 * AP1 + 8);
            al[0] = *(const uint32_t*)(pl);
            al[1] = *(const uint32_t*)(pl + 8 * AP1);
            al[2] = *(const uint32_t*)(pl + 8);
            al[3] = *(const uint32_t*)(pl + 8 * AP1 + 8);
        }
#pragma unroll
        for (int nt = 0; nt < 12; nt++) {
            int nn2 = (nt >> 2) * 64 + c0 + (nt & 3) * 8 + g;
            const uint32_t* pbh = (const uint32_t*)(sBh + nn2 * BP1 + ks * 16 + 2 * tg);
            const uint32_t* pbl = (const uint32_t*)(sBl + nn2 * BP1 + ks * 16 + 2 * tg);
            uint32_t b0h = pbh[0], b1h = pbh[4];
            uint32_t b0l = pbl[0], b1l = pbl[4];
            mma_bf16(acc[nt], ah, b0h, b1h);
            mma_bf16(acc[nt], ah, b0l, b1l);
            mma_bf16(acc[nt], al, b0h, b1h);
        }
    }

    // ---- in-register gating epilogue
#pragma unroll
    for (int rs = 0; rs < 2; rs++) {
        int row = m0 + g + rs * 8;
        long R = (long)blockIdx.x * 128 + row;
        int nb = (int)(R / 14), t = (int)(R % 14);
        float* orow = g_t1 + ((long)nb * T1 + t) * 64;
#pragma unroll
        for (int cb = 0; cb < 4; cb++) {
            int col = c0 + cb * 8 + 2 * tg;
#pragma unroll
            for (int qq = 0; qq < 2; qq++) {
                float a1 = acc[cb][rs * 2 + qq]     + sbias[col + qq];
                float a2 = acc[4 + cb][rs * 2 + qq] + sbias[64 + col + qq];
                float a3 = acc[8 + cb][rs * 2 + qq] + sbias[128 + col + qq];
                float sg = __fdividef(1.f, 1.f + __expf(-a2));
                float v  = a1 + sg + a3;
                orow[col + qq] = (v > 0.f) ? v : 0.f;
            }
        }
    }
}

// =============================================================================
// tconv2 HMMA: M=49152 (nb,t12), N=192, K=3 kc x 64. Same warp layout.
// =============================================================================
#define AP2 72
#define BP2 72
#define O2_AH   768
#define O2_AL   (O2_AH + 128*AP2*2)
#define O2_BH   (O2_AL + 128*AP2*2)
#define O2_BL   (O2_BH + 192*BP2*2)
#define SMEM_H2 (O2_BL + 192*BP2*2)   /* 92928 */

__global__ void __launch_bounds__(512, 1) k_tconv2_hmma(
    const float* __restrict__ bb1, const float* __restrict__ bb2,
    const float* __restrict__ bb3)
{
    extern __shared__ char smem[];
    float*         sbias = (float*)smem;
    __nv_bfloat16* sAh   = (__nv_bfloat16*)(smem + O2_AH);
    __nv_bfloat16* sAl   = (__nv_bfloat16*)(smem + O2_AL);
    __nv_bfloat16* sBh   = (__nv_bfloat16*)(smem + O2_BH);
    __nv_bfloat16* sBl   = (__nv_bfloat16*)(smem + O2_BL);

    int tid = threadIdx.x;
    if (tid < 64) {
        sbias[tid]       = bb1[tid];
        sbias[64 + tid]  = bb2[tid];
        sbias[128 + tid] = bb3[tid];
    }

    int lane = tid & 31, w = tid >> 5;
    int m0 = (w >> 1) * 16;
    int c0 = (w & 1) * 32;
    int g  = lane >> 2, tg = lane & 3;

    int rA = tid >> 2, quarter = tid & 3;
    long RA = (long)blockIdx.x * 128 + rA;
    int nbA = (int)(RA / 12), tA = (int)(RA % 12);

    float acc[12][4];
#pragma unroll
    for (int nt = 0; nt < 12; nt++)
#pragma unroll
        for (int q = 0; q < 4; q++) acc[nt][q] = 0.f;

    for (int kc = 0; kc < 3; kc++) {
        __syncthreads();
        // ---- stage A: 128 rows x 64 k; 4 threads/row, 16 k each
        {
            const float4* src = (const float4*)(g_t2 + ((long)nbA * T1 + tA + kc) * 64)
                                + quarter * 4;
            uint32_t off = (uint32_t)rA * (AP2 * 2) + quarter * 32;
            uint2* dh = (uint2*)((char*)sAh + off);
            uint2* dl = (uint2*)((char*)sAl + off);
#pragma unroll
            for (int v4 = 0; v4 < 4; v4++) {
                float4 xv = __ldg(&src[v4]);
                float hx = __bfloat162float(__float2bfloat16(xv.x));
                float hy = __bfloat162float(__float2bfloat16(xv.y));
                float hz = __bfloat162float(__float2bfloat16(xv.z));
                float hw = __bfloat162float(__float2bfloat16(xv.w));
                dh[v4] = make_uint2(pkbf2(hx, hy), pkbf2(hz, hw));
                dl[v4] = make_uint2(pkbf2(xv.x - hx, xv.y - hy),
                                    pkbf2(xv.z - hz, xv.w - hw));
            }
        }
        // ---- stage B for this kc
        {
            const char* bh = (const char*)(g_bh + (long)kc * 192 * 64);
            const char* bl = (const char*)(g_bl + (long)kc * 192 * 64);
            for (int u = tid; u < 192 * 8; u += 512) {
                int nn2 = u >> 3, c16 = u & 7;
                uint32_t dst = (uint32_t)nn2 * (BP2 * 2) + c16 * 16;
                *(uint4*)((char*)sBh + dst) = *(const uint4*)(bh + nn2 * 128 + c16 * 16);
                *(uint4*)((char*)sBl + dst) = *(const uint4*)(bl + nn2 * 128 + c16 * 16);
            }
        }
        __syncthreads();

#pragma unroll
        for (int ks = 0; ks < 4; ks++) {
            uint32_t ah[4], al[4];
            {
                int row = m0 + g;
                const __nv_bfloat16* ph = sAh + row * AP2 + ks * 16 + 2 * tg;
                const __nv_bfloat16* pl = sAl + row * AP2 + ks * 16 + 2 * tg;
                ah[0] = *(const uint32_t*)(ph);
                ah[1] = *(const uint32_t*)(ph + 8 * AP2);
                ah[2] = *(const uint32_t*)(ph + 8);
                ah[3] = *(const uint32_t*)(ph + 8 * AP2 + 8);
                al[0] = *(const uint32_t*)(pl);
                al[1] = *(const uint32_t*)(pl + 8 * AP2);
                al[2] = *(const uint32_t*)(pl + 8);
                al[3] = *(const uint32_t*)(pl + 8 * AP2 + 8);
            }
#pragma unroll
            for (int nt = 0; nt < 12; nt++) {
                int nn2 = (nt >> 2) * 64 + c0 + (nt & 3) * 8 + g;
                const uint32_t* pbh = (const uint32_t*)(sBh + nn2 * BP2 + ks * 16 + 2 * tg);
                const uint32_t* pbl = (const uint32_t*)(sBl + nn2 * BP2 + ks * 16 + 2 * tg);
                uint32_t b0h = pbh[0], b1h = pbh[4];
                uint32_t b0l = pbl[0], b1l = pbl[4];
                mma_bf16(acc[nt], ah, b0h, b1h);
                mma_bf16(acc[nt], ah, b0l, b1l);
                mma_bf16(acc[nt], al, b0h, b1h);
            }
        }
    }

#pragma unroll
    for (int rs = 0; rs < 2; rs++) {
        int row = m0 + g + rs * 8;
        long R = (long)blockIdx.x * 128 + row;
        int nb = (int)(R / 12), t = (int)(R % 12);
        float* orow = g_t3 + ((long)nb * T2 + t) * 64;
#pragma unroll
        for (int cb = 0; cb < 4; cb++) {
            int col = c0 + cb * 8 + 2 * tg;
#pragma unroll
            for (int qq = 0; qq < 2; qq++) {
                float a1 = acc[cb][rs * 2 + qq]     + sbias[col + qq];
                float a2 = acc[4 + cb][rs * 2 + qq] + sbias[64 + col + qq];
                float a3 = acc[8 + cb][rs * 2 + qq] + sbias[128 + col + qq];
                float sg = __fdividef(1.f, 1.f + __expf(-a2));
                float v  = a1 + sg + a3;
                orow[col + qq] = (v > 0.f) ? v : 0.f;
            }
        }
    }
}

// =============================================================================
// cheb HMMA: M=57344 rows (contiguous in g_t1/g_tx*), N=64, K=3 j x 64.
// 512 thr = 16 warps x (M16 x N64); block tile M=256. Bias+ReLU in-register.
// =============================================================================
#define APC 72
#define BPC 72
#define OC_B    256
#define OC_AH   (OC_B)
#define OC_AL   (OC_AH + 256*APC*2)
#define OC_BH   (OC_AL + 256*APC*2)
#define OC_BL   (OC_BH + 64*BPC*2)
#define SMEM_HC (OC_BL + 64*BPC*2)    /* 256 + 73728 + 18432 = 92416 */

__global__ void __launch_bounds__(512, 1) k_cheb_hmma(const float* __restrict__ bias)
{
    extern __shared__ char smem[];
    float*         sbias = (float*)smem;         // reuse low 256B
    __nv_bfloat16* sAh   = (__nv_bfloat16*)(smem + OC_AH);
    __nv_bfloat16* sAl   = (__nv_bfloat16*)(smem + OC_AL);
    __nv_bfloat16* sBh   = (__nv_bfloat16*)(smem + OC_BH);
    __nv_bfloat16* sBl   = (__nv_bfloat16*)(smem + OC_BL);

    int tid = threadIdx.x;
    // NOTE: sbias overlaps sAh start? No: OC_AH = 256, bias in [0,256). OK.
    if (tid < 64) sbias[tid] = bias[tid];

    int lane = tid & 31, w = tid >> 5;
    int m0 = w * 16;
    int g  = lane >> 2, tg = lane & 3;

    int rA = tid >> 1, half = tid & 1;
    long RA = (long)blockIdx.x * 256 + rA;

    float acc[8][4];
#pragma unroll
    for (int nt = 0; nt < 8; nt++)
#pragma unroll
        for (int q = 0; q < 4; q++) acc[nt][q] = 0.f;

    for (int j = 0; j < 3; j++) {
        __syncthreads();
        // ---- stage A chunk: 256 rows x 64 k from Txj; 2 threads/row
        {
            const float* srcj = (j == 0) ? g_t1 : ((j == 1) ? g_tx1 : g_tx2);
            const float4* src = (const float4*)(srcj + RA * 64) + half * 8;
            uint32_t off = (uint32_t)rA * (APC * 2) + half * 64;
            uint2* dh = (uint2*)((char*)sAh + off);
            uint2* dl = (uint2*)((char*)sAl + off);
#pragma unroll
            for (int v4 = 0; v4 < 8; v4++) {
                float4 xv = __ldg(&src[v4]);
                float hx = __bfloat162float(__float2bfloat16(xv.x));
                float hy = __bfloat162float(__float2bfloat16(xv.y));
                float hz = __bfloat162float(__float2bfloat16(xv.z));
                float hw = __bfloat162float(__float2bfloat16(xv.w));
                dh[v4] = make_uint2(pkbf2(hx, hy), pkbf2(hz, hw));
                dl[v4] = make_uint2(pkbf2(xv.x - hx, xv.y - hy),
                                    pkbf2(xv.z - hz, xv.w - hw));
            }
        }
        // ---- stage B chunk: 64 x 64
        if (tid < 512) {
            int u = tid;
            if (u < 64 * 8) {
                int nn2 = u >> 3, c16 = u & 7;
                uint32_t dst = (uint32_t)nn2 * (BPC * 2) + c16 * 16;
                const char* bh = (const char*)(g_chh + (long)j * 64 * 64);
                const char* bl = (const char*)(g_chl + (long)j * 64 * 64);
                *(uint4*)((char*)sBh + dst) = *(const uint4*)(bh + nn2 * 128 + c16 * 16);
                *(uint4*)((char*)sBl + dst) = *(const uint4*)(bl + nn2 * 128 + c16 * 16);
            }
        }
        __syncthreads();

#pragma unroll
        for (int ks = 0; ks < 4; ks++) {
            uint32_t ah[4], al[4];
            {
                int row = m0 + g;
                const __nv_bfloat16* ph = sAh + row * APC + ks * 16 + 2 * tg;
                const __nv_bfloat16* pl = sAl + row * APC + ks * 16 + 2 * tg;
                ah[0] = *(const uint32_t*)(ph);
                ah[1] = *(const uint32_t*)(ph + 8 * APC);
                ah[2] = *(const uint32_t*)(ph + 8);
                ah[3] = *(const uint32_t*)(ph + 8 * APC + 8);
                al[0] = *(const uint32_t*)(pl);
                al[1] = *(const uint32_t*)(pl + 8 * APC);
                al[2] = *(const uint32_t*)(pl + 8);
                al[3] = *(const uint32_t*)(pl + 8 * APC + 8);
            }
#pragma unroll
            for (int nt = 0; nt < 8; nt++) {
                int nn2 = nt * 8 + g;
                const uint32_t* pbh = (const uint32_t*)(sBh + nn2 * BPC + ks * 16 + 2 * tg);
                const uint32_t* pbl = (const uint32_t*)(sBl + nn2 * BPC + ks * 16 + 2 * tg);
                uint32_t b0h = pbh[0], b1h = pbh[4];
                uint32_t b0l = pbl[0], b1l = pbl[4];
                mma_bf16(acc[nt], ah, b0h, b1h);
                mma_bf16(acc[nt], ah, b0l, b1l);
                mma_bf16(acc[nt], al, b0h, b1h);
            }
        }
    }

    // ---- bias + relu epilogue, direct store
#pragma unroll
    for (int rs = 0; rs < 2; rs++) {
        int row = m0 + g + rs * 8;
        long R = (long)blockIdx.x * 256 + row;
        float* orow = g_t2 + R * 64;
#pragma unroll
        for (int nt = 0; nt < 8; nt++) {
            int col = nt * 8 + 2 * tg;
            float v0 = acc[nt][rs * 2 + 0] + sbias[col];
            float v1 = acc[nt][rs * 2 + 1] + sbias[col + 1];
            v0 = (v0 > 0.f) ? v0 : 0.f;
            v1 = (v1 > 0.f) ? v1 : 0.f;
            *(float2*)(orow + col) = make_float2(v0, v1);
        }
    }
}

// ---------------- ChebConv propagation (CSR gather) --------------------------
__global__ void k_prop(const float4* __restrict__ z, float4* __restrict__ out,
                       const float4* __restrict__ x0, int mode)
{
    int n = blockIdx.x;
    int tid = threadIdx.x;
    int e0 = g_rowstart[n], e1 = g_rowstart[n + 1];
    float4 acc = make_float4(0.f, 0.f, 0.f, 0.f);
    for (int e = e0; e < e1; e++) {
        int   c  = __ldg(&g_ccol[e]);
        float nm = __ldg(&g_cnorm[e]);
        float4 v = __ldg(&z[(long)c * F14 + tid]);
        acc.x += nm * v.x; acc.y += nm * v.y;
        acc.z += nm * v.z; acc.w += nm * v.w;
    }
    if (mode) {
        float4 v0 = __ldg(&x0[(long)n * F14 + tid]);
        acc.x = 2.f * acc.x - v0.x; acc.y = 2.f * acc.y - v0.y;
        acc.z = 2.f * acc.z - v0.z; acc.w = 2.f * acc.w - v0.w;
    }
    out[(long)n * F14 + tid] = acc;
}

// ---------------- BN (channel axis = node) + final transpose -----------------
__global__ void k_bn(const float* __restrict__ gamma, const float* __restrict__ beta,
                     float* __restrict__ out)
{
    int n = blockIdx.x;
    const float* tp = g_t3 + (long)n * (BB * T2 * 64);
    float s = 0.f, s2 = 0.f;
    for (int i = threadIdx.x; i < BB * T2 * 64; i += 256) {
        float v = tp[i]; s += v; s2 += v * v;
    }
    __shared__ float rs[8], rs2[8];
    for (int o = 16; o; o >>= 1) {
        s  += __shfl_down_sync(0xffffffff, s,  o);
        s2 += __shfl_down_sync(0xffffffff, s2, o);
    }
    int lane = threadIdx.x & 31, wid = threadIdx.x >> 5;
    if (lane == 0) { rs[wid] = s; rs2[wid] = s2; }
    __syncthreads();
    __shared__ float smu, srstd;
    if (wid == 0) {
        float a  = (lane < 8) ? rs[lane]  : 0.f;
        float a2 = (lane < 8) ? rs2[lane] : 0.f;
        for (int o = 4; o; o >>= 1) {
            a  += __shfl_down_sync(0xffffffff, a,  o);
            a2 += __shfl_down_sync(0xffffffff, a2, o);
        }
        if (lane == 0) {
            float mu  = a / 1536.f;
            float var = a2 / 1536.f - mu * mu;
            smu = mu; srstd = rsqrtf(var + 1e-5f);
        }
    }
    __syncthreads();
    float mu = smu, rstd = srstd;
    float ga = gamma[n], be = beta[n];
    for (int i = threadIdx.x; i < BB * T2 * 64; i += 256) {
        float v = (tp[i] - mu) * rstd * ga + be;
        int c = i & 63;
        int t = (i >> 6) % T2;
        int b = i / (T2 * 64);
        out[(((long)b * T2 + t) * NN + n) * 64 + c] = v;
    }
}

// ---------------- launch -----------------------------------------------------
extern "C" void kernel_launch(void* const* d_in, const int* in_sizes, int n_in,
                              void* d_out, int out_size)
{
    const float* X    = (const float*)d_in[0];
    const int*   ei   = (const int*)  d_in[1];
    const float* ew   = (const float*)d_in[2];
    const float* t1w1 = (const float*)d_in[3];
    const float* t1b1 = (const float*)d_in[4];
    const float* t1w2 = (const float*)d_in[5];
    const float* t1b2 = (const float*)d_in[6];
    const float* t1w3 = (const float*)d_in[7];
    const float* t1b3 = (const float*)d_in[8];
    const float* chw  = (const float*)d_in[9];
    const float* chb  = (const float*)d_in[10];
    const float* t2w1 = (const float*)d_in[11];
    const float* t2b1 = (const float*)d_in[12];
    const float* t2w2 = (const float*)d_in[13];
    const float* t2b2 = (const float*)d_in[14];
    const float* t2w3 = (const float*)d_in[15];
    const float* t2b3 = (const float*)d_in[16];
    const float* gam  = (const float*)d_in[17];
    const float* bet  = (const float*)d_in[18];
    float* out = (float*)d_out;

    void *p_t1, *p_tx1, *p_tx2;
    cudaGetSymbolAddress(&p_t1,  g_t1);
    cudaGetSymbolAddress(&p_tx1, g_tx1);
    cudaGetSymbolAddress(&p_tx2, g_tx2);

    cudaFuncSetAttribute(k_tconv1_hmma, cudaFuncAttributeMaxDynamicSharedMemorySize, SMEM_H1);
    cudaFuncSetAttribute(k_tconv2_hmma, cudaFuncAttributeMaxDynamicSharedMemorySize, SMEM_H2);
    cudaFuncSetAttribute(k_cheb_hmma,   cudaFuncAttributeMaxDynamicSharedMemorySize, SMEM_HC);

    const int NPREP = 3*192*64 + 192*96 + 3*64*64;

    k_zero   <<<(NN + 255) / 256, 256>>>();                          // 0
    k_deg    <<<EE / 256, 256>>>(ei, ew);                            // 1
    k_wprep  <<<(NPREP + 255) / 256, 256>>>(                         // 2
        t2w1, t2w2, t2w3, t1w1, t1w2, t1w3, chw);

    // 3 (profiled slot): tconv1 HMMA
    k_tconv1_hmma<<<NB_TOTAL * T1 / 128, 512, SMEM_H1>>>(X, t1b1, t1b2, t1b3);

    k_scandis<<<1, 1024>>>();                                        // 4
    k_scatter<<<EE / 256, 256>>>(ei, ew);                            // 5

    k_prop<<<NN, F14>>>((const float4*)p_t1,  (float4*)p_tx1, (const float4*)p_t1, 0);
    k_prop<<<NN, F14>>>((const float4*)p_tx1, (float4*)p_tx2, (const float4*)p_t1, 1);

    // cheb HMMA: 224 tiles of 256 rows
    k_cheb_hmma<<<NB_TOTAL * T1 / 256, 512, SMEM_HC>>>(chb);

    // tconv2 HMMA: 384 tiles
    k_tconv2_hmma<<<NB_TOTAL * T2 / 128, 512, SMEM_H2>>>(t2b1, t2b2, t2b3);

    k_bn<<<NN, 256>>>(gam, bet, out);
}